// round 14
// baseline (speedup 1.0000x reference)
#include <cuda_runtime.h>
#include <cuda_bf16.h>
#include <math.h>
#include <stdint.h>

#define Bsz 4
#define Tn  512
#define Dm  512
#define Hn  8
#define HSz 64
#define Lnum 8
#define Vn  32000
#define DFn 2048
#define NT  (Bsz*Tn)
#define EPSf 1e-5f
#define K3D (3*Dm)     // 1536
#define K3F (3*DFn)    // 6144

// ---------------- scratch ----------------------------------------------------
__device__ float g_x [NT*Dm];
__device__ float g_x2[NT*Dm];
__device__ float g_qkv[3*NT*Dm];
__device__ float g_lossrow[NT];
__device__ float g_lfb[(size_t)NT*Vn];

// bf16 triple-split activations ([M][3K], [hi,hi,lo])
__device__ __nv_bfloat16 g_xn3 [NT*K3D];
__device__ __nv_bfloat16 g_at3 [NT*K3D];
__device__ __nv_bfloat16 g_ff3 [NT*K3F];

// bf16 triple-split weights ([3K][N], rows [hi,lo,hi])
__device__ __nv_bfloat16 g_w3_uqkv [Lnum*3*(size_t)K3D*Dm];
__device__ __nv_bfloat16 g_w3_mqkv [Lnum*3*(size_t)K3D*Dm];
__device__ __nv_bfloat16 g_w3_uproj[Lnum*(size_t)K3D*Dm];
__device__ __nv_bfloat16 g_w3_mproj[Lnum*(size_t)K3D*Dm];
__device__ __nv_bfloat16 g_w3_w1   [Lnum*(size_t)K3D*DFn];
__device__ __nv_bfloat16 g_w3_w2   [Lnum*(size_t)K3F*Dm];
__device__ __nv_bfloat16 g_w3_wout [(size_t)K3D*Vn];

// ---------------- helpers ----------------------------------------------------

__device__ __forceinline__ float gelu_f(float v) {
    return 0.5f * v * (1.f + erff(v * 0.70710678118654752f));
}
__device__ __forceinline__ void store3(__nv_bfloat16* p, float v) {
    __nv_bfloat16 h = __float2bfloat16_rn(v);
    __nv_bfloat16 l = __float2bfloat16_rn(v - __bfloat162float(h));
    p[0] = h; p[1] = h; p[2] = l;
}
__device__ __forceinline__ uint32_t smem_u32(const void* p) {
    uint32_t a;
    asm("{ .reg .u64 t; cvta.to.shared.u64 t, %1; cvt.u32.u64 %0, t; }"
        : "=r"(a) : "l"(p));
    return a;
}
__device__ __forceinline__ void cp16(uint32_t dst, const void* src) {
    asm volatile("cp.async.cg.shared.global [%0], [%1], 16;"
                 :: "r"(dst), "l"(src) : "memory");
}
#define CP_COMMIT()  asm volatile("cp.async.commit_group;" ::: "memory")
template<int Nw> __device__ __forceinline__ void cp_wait() {
    asm volatile("cp.async.wait_group %0;" :: "n"(Nw) : "memory");
}
__device__ __forceinline__ void ldsm_x4(uint32_t& r0, uint32_t& r1, uint32_t& r2,
                                        uint32_t& r3, uint32_t a) {
    asm volatile("ldmatrix.sync.aligned.m8n8.x4.shared.b16 {%0,%1,%2,%3}, [%4];"
                 : "=r"(r0), "=r"(r1), "=r"(r2), "=r"(r3) : "r"(a));
}
__device__ __forceinline__ void ldsm_x4t(uint32_t& r0, uint32_t& r1, uint32_t& r2,
                                         uint32_t& r3, uint32_t a) {
    asm volatile("ldmatrix.sync.aligned.m8n8.x4.trans.shared.b16 {%0,%1,%2,%3}, [%4];"
                 : "=r"(r0), "=r"(r1), "=r"(r2), "=r"(r3) : "r"(a));
}
__device__ __forceinline__ void mma16816(float* c, const uint32_t* a, const uint32_t* b) {
    asm volatile("mma.sync.aligned.m16n8k16.row.col.f32.bf16.bf16.f32 "
                 "{%0,%1,%2,%3},{%4,%5,%6,%7},{%8,%9},{%0,%1,%2,%3};"
                 : "+f"(c[0]), "+f"(c[1]), "+f"(c[2]), "+f"(c[3])
                 : "r"(a[0]), "r"(a[1]), "r"(a[2]), "r"(a[3]), "r"(b[0]), "r"(b[1]));
}

// ---------------- weight conversion ------------------------------------------
__global__ void k_cvt_w(const float* __restrict__ W, __nv_bfloat16* __restrict__ out,
                        int K, int N, long long inz, long long outz) {
    const float* Wp = W + (size_t)blockIdx.z * inz;
    __nv_bfloat16* op = out + (size_t)blockIdx.z * outz;
    long long total = (long long)K * N;
    for (long long i = (long long)blockIdx.x * blockDim.x + threadIdx.x; i < total;
         i += (long long)gridDim.x * blockDim.x) {
        int k = (int)(i / N), n = (int)(i % N);
        float v = Wp[i];
        __nv_bfloat16 h = __float2bfloat16_rn(v);
        __nv_bfloat16 l = __float2bfloat16_rn(v - __bfloat162float(h));
        op[(size_t)(3*k+0)*N + n] = h;
        op[(size_t)(3*k+1)*N + n] = l;
        op[(size_t)(3*k+2)*N + n] = h;
    }
}

// ---------------- tensor-core GEMM -------------------------------------------
// C[M,N] = A3[M,K3] @ W3[K3,N]. BM=MT*32, BN=128, BK=64.
// 128 threads, 4 warps 2x2; warp tile (MT*16) x 64. 2-stage cp.async,
// single __syncthreads per chunk. MINB caps registers for occupancy.
template<int MT, int MINB>
__global__ void __launch_bounds__(128, MINB) k_mma(
    const __nv_bfloat16* __restrict__ A3, const __nv_bfloat16* __restrict__ W3,
    const float* __restrict__ bias, const float* __restrict__ res,
    float* __restrict__ outF, __nv_bfloat16* __restrict__ out3,
    int N, int K3, long long wz, long long bz, long long cz, int gelu) {
    constexpr int BM   = MT * 32;
    constexpr int AROW = 72;                 // padded row elems (64 + 8)
    constexpr int AST  = BM * AROW * 2;      // A stage bytes
    constexpr int BST  = 64 * 136 * 2;       // B stage bytes
    constexpr int SS   = AST + BST;
    extern __shared__ char dynsm[];
    uint32_t sbase = smem_u32(dynsm);

    if (wz) {
        W3   += (size_t)blockIdx.z * wz;
        bias += (size_t)blockIdx.z * bz;
        outF += (size_t)blockIdx.z * cz;
    }
    int tid = threadIdx.x, lane = tid & 31, warp = tid >> 5;
    int wm = warp >> 1, wn = warp & 1;
    int bm = blockIdx.y * BM, bn = blockIdx.x * 128;

    float acc[MT][8][4];
#pragma unroll
    for (int i = 0; i < MT; i++)
#pragma unroll
        for (int j = 0; j < 8; j++)
#pragma unroll
            for (int k = 0; k < 4; k++) acc[i][j][k] = 0.f;

    const int KT = K3 / 64;

    auto Aaddr = [&](int s, int r, int c) { return sbase + s*SS + (r*AROW + c)*2; };
    auto Baddr = [&](int s, int k, int n) { return sbase + s*SS + AST + (k*136 + n)*2; };

    auto fill = [&](int s, int t) {
        int k0 = t * 64;
#pragma unroll
        for (int i = 0; i < BM/16; i++) {           // A: BM x 64 elems
            int id = tid + i * 128;
            int ar = id >> 3, ac = (id & 7) * 8;
            cp16(Aaddr(s, ar, ac), A3 + (size_t)(bm + ar) * K3 + k0 + ac);
        }
#pragma unroll
        for (int i = 0; i < 8; i++) {               // B: 64 x 128 elems
            int id = tid + i * 128;
            int kk = id >> 4, nn = (id & 15) * 8;
            cp16(Baddr(s, kk, nn), W3 + (size_t)(k0 + kk) * N + bn + nn);
        }
    };

    fill(0, 0); CP_COMMIT();

    for (int t = 0; t < KT; t++) {
        int s = t & 1;
        cp_wait<0>();
        __syncthreads();
        if (t + 1 < KT) { fill(s ^ 1, t + 1); CP_COMMIT(); }
#pragma unroll
        for (int kt = 0; kt < 4; kt++) {
            int k16 = kt * 16;
            uint32_t a[MT][4];
#pragma unroll
            for (int mt = 0; mt < MT; mt++)
                ldsm_x4(a[mt][0], a[mt][1], a[mt][2], a[mt][3],
                        Aaddr(s, wm*MT*16 + mt*16 + (lane & 15), k16 + ((lane >> 4) << 3)));
            uint32_t b[8][2];
#pragma unroll
            for (int h2 = 0; h2 < 4; h2++) {
                uint32_t r0, r1, r2, r3;
                ldsm_x4t(r0, r1, r2, r3,
                         Baddr(s, k16 + (lane & 15), wn*64 + h2*16 + ((lane >> 4) << 3)));
                b[h2*2][0] = r0; b[h2*2][1] = r1;
                b[h2*2+1][0] = r2; b[h2*2+1][1] = r3;
            }
#pragma unroll
            for (int mt = 0; mt < MT; mt++)
#pragma unroll
                for (int nt = 0; nt < 8; nt++)
                    mma16816(acc[mt][nt], a[mt], b[nt]);
        }
    }

    // epilogue
    int r = lane >> 2, cg = lane & 3;
#pragma unroll
    for (int mt = 0; mt < MT; mt++) {
        int row0 = bm + wm*MT*16 + mt*16 + r;
        int row1 = row0 + 8;
#pragma unroll
        for (int nt = 0; nt < 8; nt++) {
            int col = bn + wn*64 + nt*8 + cg*2;
            float v00 = acc[mt][nt][0] + bias[col];
            float v01 = acc[mt][nt][1] + bias[col+1];
            float v10 = acc[mt][nt][2] + bias[col];
            float v11 = acc[mt][nt][3] + bias[col+1];
            if (gelu) { v00 = gelu_f(v00); v01 = gelu_f(v01);
                        v10 = gelu_f(v10); v11 = gelu_f(v11); }
            if (res) {
                float2 q0 = *(const float2*)&res[(size_t)row0*N + col];
                float2 q1 = *(const float2*)&res[(size_t)row1*N + col];
                v00 += q0.x; v01 += q0.y; v10 += q1.x; v11 += q1.y;
            }
            if (outF) {
                *(float2*)&outF[(size_t)row0*N + col] = make_float2(v00, v01);
                *(float2*)&outF[(size_t)row1*N + col] = make_float2(v10, v11);
            }
            if (out3) {
                store3(out3 + (size_t)row0*3*N + 3*col,     v00);
                store3(out3 + (size_t)row0*3*N + 3*(col+1), v01);
                store3(out3 + (size_t)row1*3*N + 3*col,     v10);
                store3(out3 + (size_t)row1*3*N + 3*(col+1), v11);
            }
        }
    }
}

// ---------------- fused attention (unchanged) --------------------------------
__global__ void __launch_bounds__(256) k_attn_fused(
    const float* __restrict__ qkv, __nv_bfloat16* __restrict__ O3, int causal) {
    extern __shared__ float sm[];
    float* Qs = sm;                 // [64][36]
    float* Ss = Qs + 64*36;         // [32][520]
    float* KV = Ss + 32*520;        // [64][68]
    int bh = blockIdx.y, b = bh >> 3, h = bh & 7;
    int t0 = blockIdx.x * 32;
    int tid = threadIdx.x;
    const float* Qg = qkv + (size_t)(b*Tn + t0)*Dm + h*HSz;
    const float* Kg = qkv + (size_t)NT*Dm + (size_t)b*Tn*Dm + h*HSz;
    const float* Vg = qkv + (size_t)2*NT*Dm + (size_t)b*Tn*Dm + h*HSz;

#pragma unroll
    for (int i = 0; i < 8; i++) {
        int id = tid + i*256;
        int k = id & 63, r2 = id >> 6;
        Qs[k*36 + r2] = Qg[(size_t)r2 * Dm + k];
    }
    int Lmax = causal ? (t0 + 32) : Tn;
    int nch = (Lmax + 63) >> 6;
    int Lpad = nch << 6;
    int tx = tid & 15, ty = tid >> 4;

    for (int c = 0; c < nch; c++) {
        int s0 = c << 6;
        __syncthreads();
#pragma unroll
        for (int i = 0; i < 16; i++) {
            int id = tid + i*256;
            int k = id & 63, s = id >> 6;
            KV[k*68 + s] = Kg[(size_t)(s0 + s) * Dm + k];
        }
        __syncthreads();
        float a0[4] = {0,0,0,0}, a1[4] = {0,0,0,0};
#pragma unroll 8
        for (int k = 0; k < 64; k++) {
            float q0 = Qs[k*36 + ty*2], q1 = Qs[k*36 + ty*2 + 1];
            float4 kv = *(const float4*)&KV[k*68 + tx*4];
            a0[0] = fmaf(q0, kv.x, a0[0]); a0[1] = fmaf(q0, kv.y, a0[1]);
            a0[2] = fmaf(q0, kv.z, a0[2]); a0[3] = fmaf(q0, kv.w, a0[3]);
            a1[0] = fmaf(q1, kv.x, a1[0]); a1[1] = fmaf(q1, kv.y, a1[1]);
            a1[2] = fmaf(q1, kv.z, a1[2]); a1[3] = fmaf(q1, kv.w, a1[3]);
        }
        int t_a = t0 + ty*2, t_b = t_a + 1;
#pragma unroll
        for (int j = 0; j < 4; j++) {
            int s = s0 + tx*4 + j;
            float v0 = a0[j] * 0.125f, v1 = a1[j] * 0.125f;
            if (causal && s > t_a) v0 = -1e30f;
            if (causal && s > t_b) v1 = -1e30f;
            Ss[(ty*2)*520 + s]   = v0;
            Ss[(ty*2+1)*520 + s] = v1;
        }
    }
    __syncthreads();

    int warp = tid >> 5, lane = tid & 31;
    for (int r2 = warp; r2 < 32; r2 += 8) {
        float mx = -1e38f;
        for (int jc = lane; jc < Lpad; jc += 32) mx = fmaxf(mx, Ss[r2*520 + jc]);
#pragma unroll
        for (int o = 16; o; o >>= 1) mx = fmaxf(mx, __shfl_xor_sync(~0u, mx, o));
        float sum = 0.f;
        for (int jc = lane; jc < Lpad; jc += 32) {
            float e = __expf(Ss[r2*520 + jc] - mx);
            Ss[r2*520 + jc] = e; sum += e;
        }
#pragma unroll
        for (int o = 16; o; o >>= 1) sum += __shfl_xor_sync(~0u, sum, o);
        float inv = 1.f / sum;
        for (int jc = lane; jc < Lpad; jc += 32) Ss[r2*520 + jc] *= inv;
    }

    float o0[4] = {0,0,0,0}, o1[4] = {0,0,0,0};
    for (int c = 0; c < nch; c++) {
        int s0 = c << 6;
        __syncthreads();
#pragma unroll
        for (int i = 0; i < 16; i++) {
            int id = tid + i*256;
            int d = id & 63, s = id >> 6;
            KV[s*68 + d] = Vg[(size_t)(s0 + s) * Dm + d];
        }
        __syncthreads();
#pragma unroll 8
        for (int s = 0; s < 64; s++) {
            float p0 = Ss[(ty*2)*520 + s0 + s];
            float p1 = Ss[(ty*2+1)*520 + s0 + s];
            float4 vv = *(const float4*)&KV[s*68 + tx*4];
            o0[0] = fmaf(p0, vv.x, o0[0]); o0[1] = fmaf(p0, vv.y, o0[1]);
            o0[2] = fmaf(p0, vv.z, o0[2]); o0[3] = fmaf(p0, vv.w, o0[3]);
            o1[0] = fmaf(p1, vv.x, o1[0]); o1[1] = fmaf(p1, vv.y, o1[1]);
            o1[2] = fmaf(p1, vv.z, o1[2]); o1[3] = fmaf(p1, vv.w, o1[3]);
        }
    }
    int row0 = b*Tn + t0 + ty*2, row1 = row0 + 1;
#pragma unroll
    for (int j = 0; j < 4; j++) {
        int col = h*HSz + tx*4 + j;
        store3(O3 + (size_t)row0*K3D + 3*col, o0[j]);
        store3(O3 + (size_t)row1*K3D + 3*col, o1[j]);
    }
}

// ---------------- other kernels ----------------------------------------------

__global__ void k_embed(const int* __restrict__ idx, const float* __restrict__ tok,
                        const float* __restrict__ pos, float* __restrict__ x) {
    int row = blockIdx.x;
    int t = row % Tn;
    int tk = idx[row];
    const float* te = tok + (size_t)tk * Dm;
    const float* pe = pos + (size_t)t  * Dm;
    float* xr = x + (size_t)row * Dm;
    for (int c = threadIdx.x; c < Dm; c += blockDim.x)
        xr[c] = te[c] + pe[c];
}

__global__ void k_layernorm3(const float* __restrict__ x, const float* __restrict__ g,
                             const float* __restrict__ b, __nv_bfloat16* __restrict__ y3) {
    __shared__ float s1[128], s2[128];
    int row = blockIdx.x;
    const float* xr = x + (size_t)row * Dm;
    __nv_bfloat16* yr = y3 + (size_t)row * K3D;
    float v[4], sum = 0.f, sq = 0.f;
#pragma unroll
    for (int i = 0; i < 4; i++) {
        v[i] = xr[threadIdx.x + i*128];
        sum += v[i]; sq += v[i]*v[i];
    }
    s1[threadIdx.x] = sum; s2[threadIdx.x] = sq; __syncthreads();
    for (int off = 64; off > 0; off >>= 1) {
        if (threadIdx.x < off) { s1[threadIdx.x] += s1[threadIdx.x+off];
                                 s2[threadIdx.x] += s2[threadIdx.x+off]; }
        __syncthreads();
    }
    float mu  = s1[0] * (1.f/Dm);
    float var = s2[0] * (1.f/Dm) - mu*mu;
    float rstd = rsqrtf(var + EPSf);
#pragma unroll
    for (int i = 0; i < 4; i++) {
        int c = threadIdx.x + i*128;
        store3(yr + 3*c, (v[i] - mu) * rstd * g[c] + b[c]);
    }
}

__global__ void k_lossrow(const float* __restrict__ logits, const int* __restrict__ tgt,
                          float* __restrict__ lr) {
    __shared__ float red[256];
    int row = blockIdx.x;
    const float* l = logits + (size_t)row * Vn;
    float mx = -1e38f;
    for (int c = threadIdx.x; c < Vn; c += 256) mx = fmaxf(mx, l[c]);
    red[threadIdx.x] = mx; __syncthreads();
    for (int off = 128; off > 0; off >>= 1) {
        if (threadIdx.x < off) red[threadIdx.x] = fmaxf(red[threadIdx.x], red[threadIdx.x+off]);
        __syncthreads();
    }
    mx = red[0]; __syncthreads();
    float s = 0.f;
    for (int c = threadIdx.x; c < Vn; c += 256) s += __expf(l[c] - mx);
    red[threadIdx.x] = s; __syncthreads();
    for (int off = 128; off > 0; off >>= 1) {
        if (threadIdx.x < off) red[threadIdx.x] += red[threadIdx.x+off];
        __syncthreads();
    }
    if (threadIdx.x == 0)
        lr[row] = mx + logf(red[0]) - l[tgt[row]];
}

__global__ void k_lossreduce(const float* __restrict__ lr, float* __restrict__ out) {
    __shared__ float red[256];
    float s = 0.f;
    for (int i = threadIdx.x; i < NT; i += 256) s += lr[i];
    red[threadIdx.x] = s; __syncthreads();
    for (int off = 128; off > 0; off >>= 1) {
        if (threadIdx.x < off) red[threadIdx.x] += red[threadIdx.x+off];
        __syncthreads();
    }
    if (threadIdx.x == 0) *out = red[0] / (float)NT;
}

// ---------------- host -------------------------------------------------------

extern "C" void kernel_launch(void* const* d_in, const int* in_sizes, int n_in,
                              void* d_out, int out_size) {
    const int*   idx  = (const int*)  d_in[0];
    const int*   tgt  = (const int*)  d_in[1];
    const float* tok  = (const float*)d_in[2];
    const float* pos  = (const float*)d_in[3];
    const float* uqw  = (const float*)d_in[4];
    const float* uqb  = (const float*)d_in[5];
    const float* upw  = (const float*)d_in[6];
    const float* upb  = (const float*)d_in[7];
    const float* mqw  = (const float*)d_in[8];
    const float* mqb  = (const float*)d_in[9];
    const float* mpw  = (const float*)d_in[10];
    const float* mpb  = (const float*)d_in[11];
    const float* w1   = (const float*)d_in[12];
    const float* b1   = (const float*)d_in[13];
    const float* w2   = (const float*)d_in[14];
    const float* b2   = (const float*)d_in[15];
    const float* g1   = (const float*)d_in[16];
    const float* bb1  = (const float*)d_in[17];
    const float* g2   = (const float*)d_in[18];
    const float* bb2  = (const float*)d_in[19];
    const float* lnfg = (const float*)d_in[20];
    const float* lnfb = (const float*)d_in[21];
    const float* wout = (const float*)d_in[22];
    const float* bout = (const float*)d_in[23];

    float *x, *x2, *qkv, *lr, *lfb;
    __nv_bfloat16 *xn3, *at3, *ff3;
    __nv_bfloat16 *wuq, *wmq, *wup, *wmp, *ww1, *ww2, *wwo;
    cudaGetSymbolAddress((void**)&x,      g_x);
    cudaGetSymbolAddress((void**)&x2,     g_x2);
    cudaGetSymbolAddress((void**)&qkv,    g_qkv);
    cudaGetSymbolAddress((void**)&lr,     g_lossrow);
    cudaGetSymbolAddress((void**)&lfb,    g_lfb);
    cudaGetSymbolAddress((void**)&xn3,    g_xn3);
    cudaGetSymbolAddress((void**)&at3,    g_at3);
    cudaGetSymbolAddress((void**)&ff3,    g_ff3);
    cudaGetSymbolAddress((void**)&wuq,    g_w3_uqkv);
    cudaGetSymbolAddress((void**)&wmq,    g_w3_mqkv);
    cudaGetSymbolAddress((void**)&wup,    g_w3_uproj);
    cudaGetSymbolAddress((void**)&wmp,    g_w3_mproj);
    cudaGetSymbolAddress((void**)&ww1,    g_w3_w1);
    cudaGetSymbolAddress((void**)&ww2,    g_w3_w2);
    cudaGetSymbolAddress((void**)&wwo,    g_w3_wout);

    const int ATT_SM = (64*36 + 32*520 + 64*68) * 4;        // 93184
    cudaFuncSetAttribute(k_attn_fused, cudaFuncAttributeMaxDynamicSharedMemorySize, ATT_SM);
    const int SM_MT1 = 2*(32*72*2 + 64*136*2);              // 44032
    const int SM_MT2 = 2*(64*72*2 + 64*136*2);              // 53248
    cudaFuncSetAttribute((const void*)&k_mma<1,4>, cudaFuncAttributeMaxDynamicSharedMemorySize, SM_MT1);
    cudaFuncSetAttribute((const void*)&k_mma<2,3>, cudaFuncAttributeMaxDynamicSharedMemorySize, SM_MT2);

    // launch order: ncu (-s 5 -c 1) captures launch index 3 -------------------
    k_cvt_w<<<dim3(512, 1, Lnum*3), 256>>>(uqw, wuq, Dm, Dm,             // 0
        (long long)Dm*Dm, (long long)K3D*Dm);
    k_embed<<<NT, 128>>>(idx, tok, pos, x);                               // 1
    k_layernorm3<<<NT, 128>>>(x, g1, bb1, xn3);                           // 2
    k_mma<2,3><<<dim3(Dm/128, NT/64, 3), 128, SM_MT2>>>(                  // 3 <- profiled
        xn3, wuq, uqb, nullptr, qkv, nullptr, Dm, K3D,
        (long long)K3D*Dm, (long long)Dm, (long long)NT*Dm, 0);
    // remaining conversions
    k_cvt_w<<<dim3(512, 1, Lnum), 256>>>(upw, wup, Dm, Dm,
        (long long)Dm*Dm, (long long)K3D*Dm);
    k_cvt_w<<<dim3(2048, 1, Lnum), 256>>>(w1, ww1, Dm, DFn,
        (long long)Dm*DFn, (long long)K3D*DFn);
    k_cvt_w<<<dim3(2048, 1, Lnum), 256>>>(w2, ww2, DFn, Dm,
        (long long)DFn*Dm, (long long)K3F*Dm);
    k_cvt_w<<<dim3(512, 1, Lnum*3), 256>>>(mqw, wmq, Dm, Dm,
        (long long)Dm*Dm, (long long)K3D*Dm);
    k_cvt_w<<<dim3(512, 1, Lnum), 256>>>(mpw, wmp, Dm, Dm,
        (long long)Dm*Dm, (long long)K3D*Dm);
    k_cvt_w<<<dim3(16384, 1, 1), 256>>>(wout, wwo, Dm, Vn, 0, 0);

    for (int l = 0; l < Lnum; l++) {
        for (int half = 0; half < 2; half++) {
            const __nv_bfloat16* qw3 = (half == 0 ? wuq : wmq) + (size_t)l * 3 * K3D * Dm;
            const __nv_bfloat16* pw3 = (half == 0 ? wup : wmp) + (size_t)l * K3D * Dm;
            const float* qb = (half == 0 ? uqb : mqb) + (size_t)l * 3 * Dm;
            const float* pb = (half == 0 ? upb : mpb) + (size_t)l * Dm;
            int causal = half;

            if (!(l == 0 && half == 0)) {
                k_layernorm3<<<NT, 128>>>(x, g1 + (size_t)l*Dm, bb1 + (size_t)l*Dm, xn3);
                k_mma<2,3><<<dim3(Dm/128, NT/64, 3), 128, SM_MT2>>>(
                    xn3, qw3, qb, nullptr, qkv, nullptr, Dm, K3D,
                    (long long)K3D*Dm, (long long)Dm, (long long)NT*Dm, 0);
            }
            k_attn_fused<<<dim3(Tn/32, Bsz*Hn), 256, ATT_SM>>>(qkv, at3, causal);
            k_mma<1,4><<<dim3(Dm/128, NT/32, 1), 128, SM_MT1>>>(
                at3, pw3, pb, x, x2, nullptr, Dm, K3D, 0, 0, 0, 0);

            k_layernorm3<<<NT, 128>>>(x2, g2 + (size_t)l*Dm, bb2 + (size_t)l*Dm, xn3);
            k_mma<2,3><<<dim3(DFn/128, NT/64, 1), 128, SM_MT2>>>(
                xn3, ww1 + (size_t)l*K3D*DFn, b1 + (size_t)l*DFn, nullptr,
                nullptr, ff3, DFn, K3D, 0, 0, 0, 1);
            k_mma<1,4><<<dim3(Dm/128, NT/32, 1), 128, SM_MT1>>>(
                ff3, ww2 + (size_t)l*K3F*Dm, b2 + (size_t)l*Dm, x2, x, nullptr,
                Dm, K3F, 0, 0, 0, 0);
        }
    }

    k_layernorm3<<<NT, 128>>>(x, lnfg, lnfb, xn3);

    long long total = (long long)NT * Vn;
    float* logits = ((long long)out_size >= total) ? (float*)d_out : lfb;
    k_mma<2,3><<<dim3(Vn/128, NT/64, 1), 128, SM_MT2>>>(
        xn3, wwo, bout, nullptr, logits, nullptr, Vn, K3D, 0, 0, 0, 0);

    k_lossrow<<<NT, 256>>>(logits, tgt, lr);

    float* lossdst;
    if ((long long)out_size >= total + 1)      lossdst = (float*)d_out + total;
    else if ((long long)out_size < total)      lossdst = (float*)d_out;
    else                                       lossdst = lr;
    k_lossreduce<<<1, 256>>>(lr, lossdst);
}

// round 15
// speedup vs baseline: 1.0232x; 1.0232x over previous
#include <cuda_runtime.h>
#include <cuda_bf16.h>
#include <math.h>
#include <stdint.h>

#define Bsz 4
#define Tn  512
#define Dm  512
#define Hn  8
#define HSz 64
#define Lnum 8
#define Vn  32000
#define DFn 2048
#define NT  (Bsz*Tn)
#define EPSf 1e-5f
#define K3D (3*Dm)     // 1536
#define K3F (3*DFn)    // 6144

// ---------------- scratch ----------------------------------------------------
__device__ float g_x [NT*Dm];
__device__ float g_x2[NT*Dm];
__device__ float g_qkv[3*NT*Dm];
__device__ float g_lossrow[NT];
__device__ float g_lfb[(size_t)NT*Vn];

// bf16 triple-split activations ([M][3K], [hi,hi,lo])
__device__ __nv_bfloat16 g_xn3 [NT*K3D];
__device__ __nv_bfloat16 g_at3 [NT*K3D];
__device__ __nv_bfloat16 g_ff3 [NT*K3F];

// bf16 triple-split weights ([3K][N], rows [hi,lo,hi])
__device__ __nv_bfloat16 g_w3_uqkv [Lnum*3*(size_t)K3D*Dm];
__device__ __nv_bfloat16 g_w3_mqkv [Lnum*3*(size_t)K3D*Dm];
__device__ __nv_bfloat16 g_w3_uproj[Lnum*(size_t)K3D*Dm];
__device__ __nv_bfloat16 g_w3_mproj[Lnum*(size_t)K3D*Dm];
__device__ __nv_bfloat16 g_w3_w1   [Lnum*(size_t)K3D*DFn];
__device__ __nv_bfloat16 g_w3_w2   [Lnum*(size_t)K3F*Dm];
__device__ __nv_bfloat16 g_w3_wout [(size_t)K3D*Vn];

// ---------------- helpers ----------------------------------------------------

__device__ __forceinline__ float gelu_f(float v) {
    return 0.5f * v * (1.f + erff(v * 0.70710678118654752f));
}
__device__ __forceinline__ void store3(__nv_bfloat16* p, float v) {
    __nv_bfloat16 h = __float2bfloat16_rn(v);
    __nv_bfloat16 l = __float2bfloat16_rn(v - __bfloat162float(h));
    p[0] = h; p[1] = h; p[2] = l;
}
__device__ __forceinline__ uint32_t smem_u32(const void* p) {
    uint32_t a;
    asm("{ .reg .u64 t; cvta.to.shared.u64 t, %1; cvt.u32.u64 %0, t; }"
        : "=r"(a) : "l"(p));
    return a;
}
__device__ __forceinline__ void cp16(uint32_t dst, const void* src) {
    asm volatile("cp.async.cg.shared.global [%0], [%1], 16;"
                 :: "r"(dst), "l"(src) : "memory");
}
#define CP_COMMIT()  asm volatile("cp.async.commit_group;" ::: "memory")
template<int Nw> __device__ __forceinline__ void cp_wait() {
    asm volatile("cp.async.wait_group %0;" :: "n"(Nw) : "memory");
}
__device__ __forceinline__ void ldsm_x4(uint32_t& r0, uint32_t& r1, uint32_t& r2,
                                        uint32_t& r3, uint32_t a) {
    asm volatile("ldmatrix.sync.aligned.m8n8.x4.shared.b16 {%0,%1,%2,%3}, [%4];"
                 : "=r"(r0), "=r"(r1), "=r"(r2), "=r"(r3) : "r"(a));
}
__device__ __forceinline__ void ldsm_x4t(uint32_t& r0, uint32_t& r1, uint32_t& r2,
                                         uint32_t& r3, uint32_t a) {
    asm volatile("ldmatrix.sync.aligned.m8n8.x4.trans.shared.b16 {%0,%1,%2,%3}, [%4];"
                 : "=r"(r0), "=r"(r1), "=r"(r2), "=r"(r3) : "r"(a));
}
__device__ __forceinline__ void mma16816(float* c, const uint32_t* a, const uint32_t* b) {
    asm volatile("mma.sync.aligned.m16n8k16.row.col.f32.bf16.bf16.f32 "
                 "{%0,%1,%2,%3},{%4,%5,%6,%7},{%8,%9},{%0,%1,%2,%3};"
                 : "+f"(c[0]), "+f"(c[1]), "+f"(c[2]), "+f"(c[3])
                 : "r"(a[0]), "r"(a[1]), "r"(a[2]), "r"(a[3]), "r"(b[0]), "r"(b[1]));
}

// ---------------- weight conversion ------------------------------------------
__global__ void k_cvt_w(const float* __restrict__ W, __nv_bfloat16* __restrict__ out,
                        int K, int N, long long inz, long long outz) {
    const float* Wp = W + (size_t)blockIdx.z * inz;
    __nv_bfloat16* op = out + (size_t)blockIdx.z * outz;
    long long total = (long long)K * N;
    for (long long i = (long long)blockIdx.x * blockDim.x + threadIdx.x; i < total;
         i += (long long)gridDim.x * blockDim.x) {
        int k = (int)(i / N), n = (int)(i % N);
        float v = Wp[i];
        __nv_bfloat16 h = __float2bfloat16_rn(v);
        __nv_bfloat16 l = __float2bfloat16_rn(v - __bfloat162float(h));
        op[(size_t)(3*k+0)*N + n] = h;
        op[(size_t)(3*k+1)*N + n] = l;
        op[(size_t)(3*k+2)*N + n] = h;
    }
}

// ---------------- tensor-core GEMM -------------------------------------------
// C[M,N] = A3[M,K3] @ W3[K3,N]. BM=MT*32, BN=128, BK=64.
// 128 threads, 4 warps 2x2; warp tile (MT*16) x 64. 2-stage cp.async,
// single __syncthreads per chunk. MINB caps registers.
template<int MT, int MINB>
__global__ void __launch_bounds__(128, MINB) k_mma(
    const __nv_bfloat16* __restrict__ A3, const __nv_bfloat16* __restrict__ W3,
    const float* __restrict__ bias, const float* __restrict__ res,
    float* __restrict__ outF, __nv_bfloat16* __restrict__ out3,
    int N, int K3, long long wz, long long bz, long long cz, int gelu) {
    constexpr int BM   = MT * 32;
    constexpr int AROW = 72;                 // padded row elems (64 + 8)
    constexpr int AST  = BM * AROW * 2;      // A stage bytes
    constexpr int BST  = 64 * 136 * 2;       // B stage bytes
    constexpr int SS   = AST + BST;
    extern __shared__ char dynsm[];
    uint32_t sbase = smem_u32(dynsm);

    if (wz) {
        W3   += (size_t)blockIdx.z * wz;
        bias += (size_t)blockIdx.z * bz;
        outF += (size_t)blockIdx.z * cz;
    }
    int tid = threadIdx.x, lane = tid & 31, warp = tid >> 5;
    int wm = warp >> 1, wn = warp & 1;
    int bm = blockIdx.y * BM, bn = blockIdx.x * 128;

    float acc[MT][8][4];
#pragma unroll
    for (int i = 0; i < MT; i++)
#pragma unroll
        for (int j = 0; j < 8; j++)
#pragma unroll
            for (int k = 0; k < 4; k++) acc[i][j][k] = 0.f;

    const int KT = K3 / 64;

    auto Aaddr = [&](int s, int r, int c) { return sbase + s*SS + (r*AROW + c)*2; };
    auto Baddr = [&](int s, int k, int n) { return sbase + s*SS + AST + (k*136 + n)*2; };

    auto fill = [&](int s, int t) {
        int k0 = t * 64;
#pragma unroll
        for (int i = 0; i < BM/16; i++) {           // A: BM x 64 elems
            int id = tid + i * 128;
            int ar = id >> 3, ac = (id & 7) * 8;
            cp16(Aaddr(s, ar, ac), A3 + (size_t)(bm + ar) * K3 + k0 + ac);
        }
#pragma unroll
        for (int i = 0; i < 8; i++) {               // B: 64 x 128 elems
            int id = tid + i * 128;
            int kk = id >> 4, nn = (id & 15) * 8;
            cp16(Baddr(s, kk, nn), W3 + (size_t)(k0 + kk) * N + bn + nn);
        }
    };

    fill(0, 0); CP_COMMIT();

    for (int t = 0; t < KT; t++) {
        int s = t & 1;
        cp_wait<0>();
        __syncthreads();
        if (t + 1 < KT) { fill(s ^ 1, t + 1); CP_COMMIT(); }
#pragma unroll
        for (int kt = 0; kt < 4; kt++) {
            int k16 = kt * 16;
            uint32_t a[MT][4];
#pragma unroll
            for (int mt = 0; mt < MT; mt++)
                ldsm_x4(a[mt][0], a[mt][1], a[mt][2], a[mt][3],
                        Aaddr(s, wm*MT*16 + mt*16 + (lane & 15), k16 + ((lane >> 4) << 3)));
            uint32_t b[8][2];
#pragma unroll
            for (int h2 = 0; h2 < 4; h2++) {
                uint32_t r0, r1, r2, r3;
                ldsm_x4t(r0, r1, r2, r3,
                         Baddr(s, k16 + (lane & 15), wn*64 + h2*16 + ((lane >> 4) << 3)));
                b[h2*2][0] = r0; b[h2*2][1] = r1;
                b[h2*2+1][0] = r2; b[h2*2+1][1] = r3;
            }
#pragma unroll
            for (int mt = 0; mt < MT; mt++)
#pragma unroll
                for (int nt = 0; nt < 8; nt++)
                    mma16816(acc[mt][nt], a[mt], b[nt]);
        }
    }

    // epilogue
    int r = lane >> 2, cg = lane & 3;
#pragma unroll
    for (int mt = 0; mt < MT; mt++) {
        int row0 = bm + wm*MT*16 + mt*16 + r;
        int row1 = row0 + 8;
#pragma unroll
        for (int nt = 0; nt < 8; nt++) {
            int col = bn + wn*64 + nt*8 + cg*2;
            float v00 = acc[mt][nt][0] + bias[col];
            float v01 = acc[mt][nt][1] + bias[col+1];
            float v10 = acc[mt][nt][2] + bias[col];
            float v11 = acc[mt][nt][3] + bias[col+1];
            if (gelu) { v00 = gelu_f(v00); v01 = gelu_f(v01);
                        v10 = gelu_f(v10); v11 = gelu_f(v11); }
            if (res) {
                float2 q0 = *(const float2*)&res[(size_t)row0*N + col];
                float2 q1 = *(const float2*)&res[(size_t)row1*N + col];
                v00 += q0.x; v01 += q0.y; v10 += q1.x; v11 += q1.y;
            }
            if (outF) {
                *(float2*)&outF[(size_t)row0*N + col] = make_float2(v00, v01);
                *(float2*)&outF[(size_t)row1*N + col] = make_float2(v10, v11);
            }
            if (out3) {
                store3(out3 + (size_t)row0*3*N + 3*col,     v00);
                store3(out3 + (size_t)row0*3*N + 3*(col+1), v01);
                store3(out3 + (size_t)row1*3*N + 3*col,     v10);
                store3(out3 + (size_t)row1*3*N + 3*(col+1), v11);
            }
        }
    }
}

// ---------------- fused attention (unchanged) --------------------------------
__global__ void __launch_bounds__(256) k_attn_fused(
    const float* __restrict__ qkv, __nv_bfloat16* __restrict__ O3, int causal) {
    extern __shared__ float sm[];
    float* Qs = sm;                 // [64][36]
    float* Ss = Qs + 64*36;         // [32][520]
    float* KV = Ss + 32*520;        // [64][68]
    int bh = blockIdx.y, b = bh >> 3, h = bh & 7;
    int t0 = blockIdx.x * 32;
    int tid = threadIdx.x;
    const float* Qg = qkv + (size_t)(b*Tn + t0)*Dm + h*HSz;
    const float* Kg = qkv + (size_t)NT*Dm + (size_t)b*Tn*Dm + h*HSz;
    const float* Vg = qkv + (size_t)2*NT*Dm + (size_t)b*Tn*Dm + h*HSz;

#pragma unroll
    for (int i = 0; i < 8; i++) {
        int id = tid + i*256;
        int k = id & 63, r2 = id >> 6;
        Qs[k*36 + r2] = Qg[(size_t)r2 * Dm + k];
    }
    int Lmax = causal ? (t0 + 32) : Tn;
    int nch = (Lmax + 63) >> 6;
    int Lpad = nch << 6;
    int tx = tid & 15, ty = tid >> 4;

    for (int c = 0; c < nch; c++) {
        int s0 = c << 6;
        __syncthreads();
#pragma unroll
        for (int i = 0; i < 16; i++) {
            int id = tid + i*256;
            int k = id & 63, s = id >> 6;
            KV[k*68 + s] = Kg[(size_t)(s0 + s) * Dm + k];
        }
        __syncthreads();
        float a0[4] = {0,0,0,0}, a1[4] = {0,0,0,0};
#pragma unroll 8
        for (int k = 0; k < 64; k++) {
            float q0 = Qs[k*36 + ty*2], q1 = Qs[k*36 + ty*2 + 1];
            float4 kv = *(const float4*)&KV[k*68 + tx*4];
            a0[0] = fmaf(q0, kv.x, a0[0]); a0[1] = fmaf(q0, kv.y, a0[1]);
            a0[2] = fmaf(q0, kv.z, a0[2]); a0[3] = fmaf(q0, kv.w, a0[3]);
            a1[0] = fmaf(q1, kv.x, a1[0]); a1[1] = fmaf(q1, kv.y, a1[1]);
            a1[2] = fmaf(q1, kv.z, a1[2]); a1[3] = fmaf(q1, kv.w, a1[3]);
        }
        int t_a = t0 + ty*2, t_b = t_a + 1;
#pragma unroll
        for (int j = 0; j < 4; j++) {
            int s = s0 + tx*4 + j;
            float v0 = a0[j] * 0.125f, v1 = a1[j] * 0.125f;
            if (causal && s > t_a) v0 = -1e30f;
            if (causal && s > t_b) v1 = -1e30f;
            Ss[(ty*2)*520 + s]   = v0;
            Ss[(ty*2+1)*520 + s] = v1;
        }
    }
    __syncthreads();

    int warp = tid >> 5, lane = tid & 31;
    for (int r2 = warp; r2 < 32; r2 += 8) {
        float mx = -1e38f;
        for (int jc = lane; jc < Lpad; jc += 32) mx = fmaxf(mx, Ss[r2*520 + jc]);
#pragma unroll
        for (int o = 16; o; o >>= 1) mx = fmaxf(mx, __shfl_xor_sync(~0u, mx, o));
        float sum = 0.f;
        for (int jc = lane; jc < Lpad; jc += 32) {
            float e = __expf(Ss[r2*520 + jc] - mx);
            Ss[r2*520 + jc] = e; sum += e;
        }
#pragma unroll
        for (int o = 16; o; o >>= 1) sum += __shfl_xor_sync(~0u, sum, o);
        float inv = 1.f / sum;
        for (int jc = lane; jc < Lpad; jc += 32) Ss[r2*520 + jc] *= inv;
    }

    float o0[4] = {0,0,0,0}, o1[4] = {0,0,0,0};
    for (int c = 0; c < nch; c++) {
        int s0 = c << 6;
        __syncthreads();
#pragma unroll
        for (int i = 0; i < 16; i++) {
            int id = tid + i*256;
            int d = id & 63, s = id >> 6;
            KV[s*68 + d] = Vg[(size_t)(s0 + s) * Dm + d];
        }
        __syncthreads();
#pragma unroll 8
        for (int s = 0; s < 64; s++) {
            float p0 = Ss[(ty*2)*520 + s0 + s];
            float p1 = Ss[(ty*2+1)*520 + s0 + s];
            float4 vv = *(const float4*)&KV[s*68 + tx*4];
            o0[0] = fmaf(p0, vv.x, o0[0]); o0[1] = fmaf(p0, vv.y, o0[1]);
            o0[2] = fmaf(p0, vv.z, o0[2]); o0[3] = fmaf(p0, vv.w, o0[3]);
            o1[0] = fmaf(p1, vv.x, o1[0]); o1[1] = fmaf(p1, vv.y, o1[1]);
            o1[2] = fmaf(p1, vv.z, o1[2]); o1[3] = fmaf(p1, vv.w, o1[3]);
        }
    }
    int row0 = b*Tn + t0 + ty*2, row1 = row0 + 1;
#pragma unroll
    for (int j = 0; j < 4; j++) {
        int col = h*HSz + tx*4 + j;
        store3(O3 + (size_t)row0*K3D + 3*col, o0[j]);
        store3(O3 + (size_t)row1*K3D + 3*col, o1[j]);
    }
}

// ---------------- other kernels ----------------------------------------------

__global__ void k_embed(const int* __restrict__ idx, const float* __restrict__ tok,
                        const float* __restrict__ pos, float* __restrict__ x) {
    int row = blockIdx.x;
    int t = row % Tn;
    int tk = idx[row];
    const float* te = tok + (size_t)tk * Dm;
    const float* pe = pos + (size_t)t  * Dm;
    float* xr = x + (size_t)row * Dm;
    for (int c = threadIdx.x; c < Dm; c += blockDim.x)
        xr[c] = te[c] + pe[c];
}

__global__ void k_layernorm3(const float* __restrict__ x, const float* __restrict__ g,
                             const float* __restrict__ b, __nv_bfloat16* __restrict__ y3) {
    __shared__ float s1[128], s2[128];
    int row = blockIdx.x;
    const float* xr = x + (size_t)row * Dm;
    __nv_bfloat16* yr = y3 + (size_t)row * K3D;
    float v[4], sum = 0.f, sq = 0.f;
#pragma unroll
    for (int i = 0; i < 4; i++) {
        v[i] = xr[threadIdx.x + i*128];
        sum += v[i]; sq += v[i]*v[i];
    }
    s1[threadIdx.x] = sum; s2[threadIdx.x] = sq; __syncthreads();
    for (int off = 64; off > 0; off >>= 1) {
        if (threadIdx.x < off) { s1[threadIdx.x] += s1[threadIdx.x+off];
                                 s2[threadIdx.x] += s2[threadIdx.x+off]; }
        __syncthreads();
    }
    float mu  = s1[0] * (1.f/Dm);
    float var = s2[0] * (1.f/Dm) - mu*mu;
    float rstd = rsqrtf(var + EPSf);
#pragma unroll
    for (int i = 0; i < 4; i++) {
        int c = threadIdx.x + i*128;
        store3(yr + 3*c, (v[i] - mu) * rstd * g[c] + b[c]);
    }
}

__global__ void k_lossrow(const float* __restrict__ logits, const int* __restrict__ tgt,
                          float* __restrict__ lr) {
    __shared__ float red[256];
    int row = blockIdx.x;
    const float* l = logits + (size_t)row * Vn;
    float mx = -1e38f;
    for (int c = threadIdx.x; c < Vn; c += 256) mx = fmaxf(mx, l[c]);
    red[threadIdx.x] = mx; __syncthreads();
    for (int off = 128; off > 0; off >>= 1) {
        if (threadIdx.x < off) red[threadIdx.x] = fmaxf(red[threadIdx.x], red[threadIdx.x+off]);
        __syncthreads();
    }
    mx = red[0]; __syncthreads();
    float s = 0.f;
    for (int c = threadIdx.x; c < Vn; c += 256) s += __expf(l[c] - mx);
    red[threadIdx.x] = s; __syncthreads();
    for (int off = 128; off > 0; off >>= 1) {
        if (threadIdx.x < off) red[threadIdx.x] += red[threadIdx.x+off];
        __syncthreads();
    }
    if (threadIdx.x == 0)
        lr[row] = mx + logf(red[0]) - l[tgt[row]];
}

__global__ void k_lossreduce(const float* __restrict__ lr, float* __restrict__ out) {
    __shared__ float red[256];
    float s = 0.f;
    for (int i = threadIdx.x; i < NT; i += 256) s += lr[i];
    red[threadIdx.x] = s; __syncthreads();
    for (int off = 128; off > 0; off >>= 1) {
        if (threadIdx.x < off) red[threadIdx.x] += red[threadIdx.x+off];
        __syncthreads();
    }
    if (threadIdx.x == 0) *out = red[0] / (float)NT;
}

// ---------------- host -------------------------------------------------------

extern "C" void kernel_launch(void* const* d_in, const int* in_sizes, int n_in,
                              void* d_out, int out_size) {
    const int*   idx  = (const int*)  d_in[0];
    const int*   tgt  = (const int*)  d_in[1];
    const float* tok  = (const float*)d_in[2];
    const float* pos  = (const float*)d_in[3];
    const float* uqw  = (const float*)d_in[4];
    const float* uqb  = (const float*)d_in[5];
    const float* upw  = (const float*)d_in[6];
    const float* upb  = (const float*)d_in[7];
    const float* mqw  = (const float*)d_in[8];
    const float* mqb  = (const float*)d_in[9];
    const float* mpw  = (const float*)d_in[10];
    const float* mpb  = (const float*)d_in[11];
    const float* w1   = (const float*)d_in[12];
    const float* b1   = (const float*)d_in[13];
    const float* w2   = (const float*)d_in[14];
    const float* b2   = (const float*)d_in[15];
    const float* g1   = (const float*)d_in[16];
    const float* bb1  = (const float*)d_in[17];
    const float* g2   = (const float*)d_in[18];
    const float* bb2  = (const float*)d_in[19];
    const float* lnfg = (const float*)d_in[20];
    const float* lnfb = (const float*)d_in[21];
    const float* wout = (const float*)d_in[22];
    const float* bout = (const float*)d_in[23];

    float *x, *x2, *qkv, *lr, *lfb;
    __nv_bfloat16 *xn3, *at3, *ff3;
    __nv_bfloat16 *wuq, *wmq, *wup, *wmp, *ww1, *ww2, *wwo;
    cudaGetSymbolAddress((void**)&x,      g_x);
    cudaGetSymbolAddress((void**)&x2,     g_x2);
    cudaGetSymbolAddress((void**)&qkv,    g_qkv);
    cudaGetSymbolAddress((void**)&lr,     g_lossrow);
    cudaGetSymbolAddress((void**)&lfb,    g_lfb);
    cudaGetSymbolAddress((void**)&xn3,    g_xn3);
    cudaGetSymbolAddress((void**)&at3,    g_at3);
    cudaGetSymbolAddress((void**)&ff3,    g_ff3);
    cudaGetSymbolAddress((void**)&wuq,    g_w3_uqkv);
    cudaGetSymbolAddress((void**)&wmq,    g_w3_mqkv);
    cudaGetSymbolAddress((void**)&wup,    g_w3_uproj);
    cudaGetSymbolAddress((void**)&wmp,    g_w3_mproj);
    cudaGetSymbolAddress((void**)&ww1,    g_w3_w1);
    cudaGetSymbolAddress((void**)&ww2,    g_w3_w2);
    cudaGetSymbolAddress((void**)&wwo,    g_w3_wout);

    const int ATT_SM = (64*36 + 32*520 + 64*68) * 4;        // 93184
    cudaFuncSetAttribute(k_attn_fused, cudaFuncAttributeMaxDynamicSharedMemorySize, ATT_SM);
    const int SM_MT2 = 2*(64*72*2  + 64*136*2);             // 53248
    const int SM_MT4 = 2*(128*72*2 + 64*136*2);             // 71680
    cudaFuncSetAttribute((const void*)&k_mma<2,3>, cudaFuncAttributeMaxDynamicSharedMemorySize, SM_MT2);
    cudaFuncSetAttribute((const void*)&k_mma<4,2>, cudaFuncAttributeMaxDynamicSharedMemorySize, SM_MT4);

    // launch order: ncu (-s 5 -c 1) captures launch index 3 -------------------
    k_cvt_w<<<dim3(512, 1, Lnum*3), 256>>>(uqw, wuq, Dm, Dm,             // 0
        (long long)Dm*Dm, (long long)K3D*Dm);
    k_embed<<<NT, 128>>>(idx, tok, pos, x);                               // 1
    k_layernorm3<<<NT, 128>>>(x, g1, bb1, xn3);                           // 2
    k_mma<2,3><<<dim3(Dm/128, NT/64, 3), 128, SM_MT2>>>(                  // 3 <- profiled
        xn3, wuq, uqb, nullptr, qkv, nullptr, Dm, K3D,
        (long long)K3D*Dm, (long long)Dm, (long long)NT*Dm, 0);
    // remaining conversions
    k_cvt_w<<<dim3(512, 1, Lnum), 256>>>(upw, wup, Dm, Dm,
        (long long)Dm*Dm, (long long)K3D*Dm);
    k_cvt_w<<<dim3(2048, 1, Lnum), 256>>>(w1, ww1, Dm, DFn,
        (long long)Dm*DFn, (long long)K3D*DFn);
    k_cvt_w<<<dim3(2048, 1, Lnum), 256>>>(w2, ww2, DFn, Dm,
        (long long)DFn*Dm, (long long)K3F*Dm);
    k_cvt_w<<<dim3(512, 1, Lnum*3), 256>>>(mqw, wmq, Dm, Dm,
        (long long)Dm*Dm, (long long)K3D*Dm);
    k_cvt_w<<<dim3(512, 1, Lnum), 256>>>(mpw, wmp, Dm, Dm,
        (long long)Dm*Dm, (long long)K3D*Dm);
    k_cvt_w<<<dim3(16384, 1, 1), 256>>>(wout, wwo, Dm, Vn, 0, 0);

    for (int l = 0; l < Lnum; l++) {
        for (int half = 0; half < 2; half++) {
            const __nv_bfloat16* qw3 = (half == 0 ? wuq : wmq) + (size_t)l * 3 * K3D * Dm;
            const __nv_bfloat16* pw3 = (half == 0 ? wup : wmp) + (size_t)l * K3D * Dm;
            const float* qb = (half == 0 ? uqb : mqb) + (size_t)l * 3 * Dm;
            const float* pb = (half == 0 ? upb : mpb) + (size_t)l * Dm;
            int causal = half;

            if (!(l == 0 && half == 0)) {
                k_layernorm3<<<NT, 128>>>(x, g1 + (size_t)l*Dm, bb1 + (size_t)l*Dm, xn3);
                k_mma<2,3><<<dim3(Dm/128, NT/64, 3), 128, SM_MT2>>>(
                    xn3, qw3, qb, nullptr, qkv, nullptr, Dm, K3D,
                    (long long)K3D*Dm, (long long)Dm, (long long)NT*Dm, 0);
            }
            k_attn_fused<<<dim3(Tn/32, Bsz*Hn), 256, ATT_SM>>>(qkv, at3, causal);
            k_mma<2,3><<<dim3(Dm/128, NT/64, 1), 128, SM_MT2>>>(
                at3, pw3, pb, x, x2, nullptr, Dm, K3D, 0, 0, 0, 0);

            k_layernorm3<<<NT, 128>>>(x2, g2 + (size_t)l*Dm, bb2 + (size_t)l*Dm, xn3);
            k_mma<4,2><<<dim3(DFn/128, NT/128, 1), 128, SM_MT4>>>(
                xn3, ww1 + (size_t)l*K3D*DFn, b1 + (size_t)l*DFn, nullptr,
                nullptr, ff3, DFn, K3D, 0, 0, 0, 1);
            k_mma<2,3><<<dim3(Dm/128, NT/64, 1), 128, SM_MT2>>>(
                ff3, ww2 + (size_t)l*K3F*Dm, b2 + (size_t)l*Dm, x2, x, nullptr,
                Dm, K3F, 0, 0, 0, 0);
        }
    }

    k_layernorm3<<<NT, 128>>>(x, lnfg, lnfb, xn3);

    long long total = (long long)NT * Vn;
    float* logits = ((long long)out_size >= total) ? (float*)d_out : lfb;
    k_mma<4,2><<<dim3(Vn/128, NT/128, 1), 128, SM_MT4>>>(
        xn3, wwo, bout, nullptr, logits, nullptr, Vn, K3D, 0, 0, 0, 0);

    k_lossrow<<<NT, 256>>>(logits, tgt, lr);

    float* lossdst;
    if ((long long)out_size >= total + 1)      lossdst = (float*)d_out + total;
    else if ((long long)out_size < total)      lossdst = (float*)d_out;
    else                                       lossdst = lr;
    k_lossreduce<<<1, 256>>>(lr, lossdst);
}

// round 16
// speedup vs baseline: 1.0800x; 1.0555x over previous
#include <cuda_runtime.h>
#include <cuda_bf16.h>
#include <math.h>
#include <stdint.h>

#define Bsz 4
#define Tn  512
#define Dm  512
#define Hn  8
#define HSz 64
#define Lnum 8
#define Vn  32000
#define DFn 2048
#define NT  (Bsz*Tn)
#define EPSf 1e-5f
#define K3D (3*Dm)     // 1536
#define K3F (3*DFn)    // 6144

// ---------------- scratch ----------------------------------------------------
__device__ float g_x [NT*Dm];
__device__ float g_x2[NT*Dm];
__device__ float g_qkv[3*NT*Dm];
__device__ float g_lossrow[NT];
__device__ float g_lfb[(size_t)NT*Vn];

// bf16 triple-split activations ([M][3K], [hi,hi,lo])
__device__ __nv_bfloat16 g_xn3 [NT*K3D];
__device__ __nv_bfloat16 g_at3 [NT*K3D];
__device__ __nv_bfloat16 g_ff3 [NT*K3F];

// bf16 triple-split weights ([3K][N], rows [hi,lo,hi])
__device__ __nv_bfloat16 g_w3_uqkv [Lnum*3*(size_t)K3D*Dm];
__device__ __nv_bfloat16 g_w3_mqkv [Lnum*3*(size_t)K3D*Dm];
__device__ __nv_bfloat16 g_w3_uproj[Lnum*(size_t)K3D*Dm];
__device__ __nv_bfloat16 g_w3_mproj[Lnum*(size_t)K3D*Dm];
__device__ __nv_bfloat16 g_w3_w1   [Lnum*(size_t)K3D*DFn];
__device__ __nv_bfloat16 g_w3_w2   [Lnum*(size_t)K3F*Dm];
__device__ __nv_bfloat16 g_w3_wout [(size_t)K3D*Vn];

// ---------------- helpers ----------------------------------------------------

__device__ __forceinline__ float gelu_f(float v) {
    return 0.5f * v * (1.f + erff(v * 0.70710678118654752f));
}
__device__ __forceinline__ void store3(__nv_bfloat16* p, float v) {
    __nv_bfloat16 h = __float2bfloat16_rn(v);
    __nv_bfloat16 l = __float2bfloat16_rn(v - __bfloat162float(h));
    p[0] = h; p[1] = h; p[2] = l;
}
__device__ __forceinline__ uint32_t smem_u32(const void* p) {
    uint32_t a;
    asm("{ .reg .u64 t; cvta.to.shared.u64 t, %1; cvt.u32.u64 %0, t; }"
        : "=r"(a) : "l"(p));
    return a;
}
__device__ __forceinline__ void cp16(uint32_t dst, const void* src) {
    asm volatile("cp.async.cg.shared.global [%0], [%1], 16;"
                 :: "r"(dst), "l"(src) : "memory");
}
#define CP_COMMIT()  asm volatile("cp.async.commit_group;" ::: "memory")
template<int Nw> __device__ __forceinline__ void cp_wait() {
    asm volatile("cp.async.wait_group %0;" :: "n"(Nw) : "memory");
}
__device__ __forceinline__ void ldsm_x4(uint32_t& r0, uint32_t& r1, uint32_t& r2,
                                        uint32_t& r3, uint32_t a) {
    asm volatile("ldmatrix.sync.aligned.m8n8.x4.shared.b16 {%0,%1,%2,%3}, [%4];"
                 : "=r"(r0), "=r"(r1), "=r"(r2), "=r"(r3) : "r"(a));
}
__device__ __forceinline__ void ldsm_x4t(uint32_t& r0, uint32_t& r1, uint32_t& r2,
                                         uint32_t& r3, uint32_t a) {
    asm volatile("ldmatrix.sync.aligned.m8n8.x4.trans.shared.b16 {%0,%1,%2,%3}, [%4];"
                 : "=r"(r0), "=r"(r1), "=r"(r2), "=r"(r3) : "r"(a));
}
__device__ __forceinline__ void mma16816(float* c, const uint32_t* a, const uint32_t* b) {
    asm volatile("mma.sync.aligned.m16n8k16.row.col.f32.bf16.bf16.f32 "
                 "{%0,%1,%2,%3},{%4,%5,%6,%7},{%8,%9},{%0,%1,%2,%3};"
                 : "+f"(c[0]), "+f"(c[1]), "+f"(c[2]), "+f"(c[3])
                 : "r"(a[0]), "r"(a[1]), "r"(a[2]), "r"(a[3]), "r"(b[0]), "r"(b[1]));
}

// ---------------- weight conversion ------------------------------------------
__global__ void k_cvt_w(const float* __restrict__ W, __nv_bfloat16* __restrict__ out,
                        int K, int N, long long inz, long long outz) {
    const float* Wp = W + (size_t)blockIdx.z * inz;
    __nv_bfloat16* op = out + (size_t)blockIdx.z * outz;
    long long total = (long long)K * N;
    for (long long i = (long long)blockIdx.x * blockDim.x + threadIdx.x; i < total;
         i += (long long)gridDim.x * blockDim.x) {
        int k = (int)(i / N), n = (int)(i % N);
        float v = Wp[i];
        __nv_bfloat16 h = __float2bfloat16_rn(v);
        __nv_bfloat16 l = __float2bfloat16_rn(v - __bfloat162float(h));
        op[(size_t)(3*k+0)*N + n] = h;
        op[(size_t)(3*k+1)*N + n] = l;
        op[(size_t)(3*k+2)*N + n] = h;
    }
}

// ---------------- tensor-core GEMM -------------------------------------------
// C[M,N] = A3[M,K3] @ W3[K3,N]. BM=MT*32, BN=128, BK=64.
// 128 threads, 4 warps 2x2; warp tile (MT*16) x 64. STG-stage cp.async,
// single __syncthreads per chunk. STG=2 for fat grids, STG=3 for thin grids.
template<int MT, int MINB, int STG>
__global__ void __launch_bounds__(128, MINB) k_mma(
    const __nv_bfloat16* __restrict__ A3, const __nv_bfloat16* __restrict__ W3,
    const float* __restrict__ bias, const float* __restrict__ res,
    float* __restrict__ outF, __nv_bfloat16* __restrict__ out3,
    int N, int K3, long long wz, long long bz, long long cz, int gelu) {
    constexpr int BM   = MT * 32;
    constexpr int AROW = 72;                 // padded row elems (64 + 8)
    constexpr int AST  = BM * AROW * 2;      // A stage bytes
    constexpr int BST  = 64 * 136 * 2;       // B stage bytes
    constexpr int SS   = AST + BST;
    extern __shared__ char dynsm[];
    uint32_t sbase = smem_u32(dynsm);

    if (wz) {
        W3   += (size_t)blockIdx.z * wz;
        bias += (size_t)blockIdx.z * bz;
        outF += (size_t)blockIdx.z * cz;
    }
    int tid = threadIdx.x, lane = tid & 31, warp = tid >> 5;
    int wm = warp >> 1, wn = warp & 1;
    int bm = blockIdx.y * BM, bn = blockIdx.x * 128;

    float acc[MT][8][4];
#pragma unroll
    for (int i = 0; i < MT; i++)
#pragma unroll
        for (int j = 0; j < 8; j++)
#pragma unroll
            for (int k = 0; k < 4; k++) acc[i][j][k] = 0.f;

    const int KT = K3 / 64;

    auto Aaddr = [&](int s, int r, int c) { return sbase + s*SS + (r*AROW + c)*2; };
    auto Baddr = [&](int s, int k, int n) { return sbase + s*SS + AST + (k*136 + n)*2; };

    auto fill = [&](int s, int t) {
        int k0 = t * 64;
#pragma unroll
        for (int i = 0; i < BM/16; i++) {           // A: BM x 64 elems
            int id = tid + i * 128;
            int ar = id >> 3, ac = (id & 7) * 8;
            cp16(Aaddr(s, ar, ac), A3 + (size_t)(bm + ar) * K3 + k0 + ac);
        }
#pragma unroll
        for (int i = 0; i < 8; i++) {               // B: 64 x 128 elems
            int id = tid + i * 128;
            int kk = id >> 4, nn = (id & 15) * 8;
            cp16(Baddr(s, kk, nn), W3 + (size_t)(k0 + kk) * N + bn + nn);
        }
    };

    fill(0, 0); CP_COMMIT();
    if (STG == 3) { fill(1, 1); CP_COMMIT(); }

    for (int t = 0; t < KT; t++) {
        int s = t % STG;
        if (STG == 2) {
            cp_wait<0>();
            __syncthreads();
            if (t + 1 < KT) { fill((t + 1) % STG, t + 1); CP_COMMIT(); }
        } else {
            if (t + 1 < KT) cp_wait<1>(); else cp_wait<0>();
            __syncthreads();
            if (t + 2 < KT) { fill((t + 2) % STG, t + 2); CP_COMMIT(); }
        }
#pragma unroll
        for (int kt = 0; kt < 4; kt++) {
            int k16 = kt * 16;
            uint32_t a[MT][4];
#pragma unroll
            for (int mt = 0; mt < MT; mt++)
                ldsm_x4(a[mt][0], a[mt][1], a[mt][2], a[mt][3],
                        Aaddr(s, wm*MT*16 + mt*16 + (lane & 15), k16 + ((lane >> 4) << 3)));
            uint32_t b[8][2];
#pragma unroll
            for (int h2 = 0; h2 < 4; h2++) {
                uint32_t r0, r1, r2, r3;
                ldsm_x4t(r0, r1, r2, r3,
                         Baddr(s, k16 + (lane & 15), wn*64 + h2*16 + ((lane >> 4) << 3)));
                b[h2*2][0] = r0; b[h2*2][1] = r1;
                b[h2*2+1][0] = r2; b[h2*2+1][1] = r3;
            }
#pragma unroll
            for (int mt = 0; mt < MT; mt++)
#pragma unroll
                for (int nt = 0; nt < 8; nt++)
                    mma16816(acc[mt][nt], a[mt], b[nt]);
        }
    }

    // epilogue
    int r = lane >> 2, cg = lane & 3;
#pragma unroll
    for (int mt = 0; mt < MT; mt++) {
        int row0 = bm + wm*MT*16 + mt*16 + r;
        int row1 = row0 + 8;
#pragma unroll
        for (int nt = 0; nt < 8; nt++) {
            int col = bn + wn*64 + nt*8 + cg*2;
            float v00 = acc[mt][nt][0] + bias[col];
            float v01 = acc[mt][nt][1] + bias[col+1];
            float v10 = acc[mt][nt][2] + bias[col];
            float v11 = acc[mt][nt][3] + bias[col+1];
            if (gelu) { v00 = gelu_f(v00); v01 = gelu_f(v01);
                        v10 = gelu_f(v10); v11 = gelu_f(v11); }
            if (res) {
                float2 q0 = *(const float2*)&res[(size_t)row0*N + col];
                float2 q1 = *(const float2*)&res[(size_t)row1*N + col];
                v00 += q0.x; v01 += q0.y; v10 += q1.x; v11 += q1.y;
            }
            if (outF) {
                *(float2*)&outF[(size_t)row0*N + col] = make_float2(v00, v01);
                *(float2*)&outF[(size_t)row1*N + col] = make_float2(v10, v11);
            }
            if (out3) {
                store3(out3 + (size_t)row0*3*N + 3*col,     v00);
                store3(out3 + (size_t)row0*3*N + 3*(col+1), v01);
                store3(out3 + (size_t)row1*3*N + 3*col,     v10);
                store3(out3 + (size_t)row1*3*N + 3*(col+1), v11);
            }
        }
    }
}

// ---------------- fused attention (unchanged) --------------------------------
__global__ void __launch_bounds__(256) k_attn_fused(
    const float* __restrict__ qkv, __nv_bfloat16* __restrict__ O3, int causal) {
    extern __shared__ float sm[];
    float* Qs = sm;                 // [64][36]
    float* Ss = Qs + 64*36;         // [32][520]
    float* KV = Ss + 32*520;        // [64][68]
    int bh = blockIdx.y, b = bh >> 3, h = bh & 7;
    int t0 = blockIdx.x * 32;
    int tid = threadIdx.x;
    const float* Qg = qkv + (size_t)(b*Tn + t0)*Dm + h*HSz;
    const float* Kg = qkv + (size_t)NT*Dm + (size_t)b*Tn*Dm + h*HSz;
    const float* Vg = qkv + (size_t)2*NT*Dm + (size_t)b*Tn*Dm + h*HSz;

#pragma unroll
    for (int i = 0; i < 8; i++) {
        int id = tid + i*256;
        int k = id & 63, r2 = id >> 6;
        Qs[k*36 + r2] = Qg[(size_t)r2 * Dm + k];
    }
    int Lmax = causal ? (t0 + 32) : Tn;
    int nch = (Lmax + 63) >> 6;
    int Lpad = nch << 6;
    int tx = tid & 15, ty = tid >> 4;

    for (int c = 0; c < nch; c++) {
        int s0 = c << 6;
        __syncthreads();
#pragma unroll
        for (int i = 0; i < 16; i++) {
            int id = tid + i*256;
            int k = id & 63, s = id >> 6;
            KV[k*68 + s] = Kg[(size_t)(s0 + s) * Dm + k];
        }
        __syncthreads();
        float a0[4] = {0,0,0,0}, a1[4] = {0,0,0,0};
#pragma unroll 8
        for (int k = 0; k < 64; k++) {
            float q0 = Qs[k*36 + ty*2], q1 = Qs[k*36 + ty*2 + 1];
            float4 kv = *(const float4*)&KV[k*68 + tx*4];
            a0[0] = fmaf(q0, kv.x, a0[0]); a0[1] = fmaf(q0, kv.y, a0[1]);
            a0[2] = fmaf(q0, kv.z, a0[2]); a0[3] = fmaf(q0, kv.w, a0[3]);
            a1[0] = fmaf(q1, kv.x, a1[0]); a1[1] = fmaf(q1, kv.y, a1[1]);
            a1[2] = fmaf(q1, kv.z, a1[2]); a1[3] = fmaf(q1, kv.w, a1[3]);
        }
        int t_a = t0 + ty*2, t_b = t_a + 1;
#pragma unroll
        for (int j = 0; j < 4; j++) {
            int s = s0 + tx*4 + j;
            float v0 = a0[j] * 0.125f, v1 = a1[j] * 0.125f;
            if (causal && s > t_a) v0 = -1e30f;
            if (causal && s > t_b) v1 = -1e30f;
            Ss[(ty*2)*520 + s]   = v0;
            Ss[(ty*2+1)*520 + s] = v1;
        }
    }
    __syncthreads();

    int warp = tid >> 5, lane = tid & 31;
    for (int r2 = warp; r2 < 32; r2 += 8) {
        float mx = -1e38f;
        for (int jc = lane; jc < Lpad; jc += 32) mx = fmaxf(mx, Ss[r2*520 + jc]);
#pragma unroll
        for (int o = 16; o; o >>= 1) mx = fmaxf(mx, __shfl_xor_sync(~0u, mx, o));
        float sum = 0.f;
        for (int jc = lane; jc < Lpad; jc += 32) {
            float e = __expf(Ss[r2*520 + jc] - mx);
            Ss[r2*520 + jc] = e; sum += e;
        }
#pragma unroll
        for (int o = 16; o; o >>= 1) sum += __shfl_xor_sync(~0u, sum, o);
        float inv = 1.f / sum;
        for (int jc = lane; jc < Lpad; jc += 32) Ss[r2*520 + jc] *= inv;
    }

    float o0[4] = {0,0,0,0}, o1[4] = {0,0,0,0};
    for (int c = 0; c < nch; c++) {
        int s0 = c << 6;
        __syncthreads();
#pragma unroll
        for (int i = 0; i < 16; i++) {
            int id = tid + i*256;
            int d = id & 63, s = id >> 6;
            KV[s*68 + d] = Vg[(size_t)(s0 + s) * Dm + d];
        }
        __syncthreads();
#pragma unroll 8
        for (int s = 0; s < 64; s++) {
            float p0 = Ss[(ty*2)*520 + s0 + s];
            float p1 = Ss[(ty*2+1)*520 + s0 + s];
            float4 vv = *(const float4*)&KV[s*68 + tx*4];
            o0[0] = fmaf(p0, vv.x, o0[0]); o0[1] = fmaf(p0, vv.y, o0[1]);
            o0[2] = fmaf(p0, vv.z, o0[2]); o0[3] = fmaf(p0, vv.w, o0[3]);
            o1[0] = fmaf(p1, vv.x, o1[0]); o1[1] = fmaf(p1, vv.y, o1[1]);
            o1[2] = fmaf(p1, vv.z, o1[2]); o1[3] = fmaf(p1, vv.w, o1[3]);
        }
    }
    int row0 = b*Tn + t0 + ty*2, row1 = row0 + 1;
#pragma unroll
    for (int j = 0; j < 4; j++) {
        int col = h*HSz + tx*4 + j;
        store3(O3 + (size_t)row0*K3D + 3*col, o0[j]);
        store3(O3 + (size_t)row1*K3D + 3*col, o1[j]);
    }
}

// ---------------- other kernels ----------------------------------------------

__global__ void k_embed(const int* __restrict__ idx, const float* __restrict__ tok,
                        const float* __restrict__ pos, float* __restrict__ x) {
    int row = blockIdx.x;
    int t = row % Tn;
    int tk = idx[row];
    const float* te = tok + (size_t)tk * Dm;
    const float* pe = pos + (size_t)t  * Dm;
    float* xr = x + (size_t)row * Dm;
    for (int c = threadIdx.x; c < Dm; c += blockDim.x)
        xr[c] = te[c] + pe[c];
}

__global__ void k_layernorm3(const float* __restrict__ x, const float* __restrict__ g,
                             const float* __restrict__ b, __nv_bfloat16* __restrict__ y3) {
    __shared__ float s1[128], s2[128];
    int row = blockIdx.x;
    const float* xr = x + (size_t)row * Dm;
    __nv_bfloat16* yr = y3 + (size_t)row * K3D;
    float v[4], sum = 0.f, sq = 0.f;
#pragma unroll
    for (int i = 0; i < 4; i++) {
        v[i] = xr[threadIdx.x + i*128];
        sum += v[i]; sq += v[i]*v[i];
    }
    s1[threadIdx.x] = sum; s2[threadIdx.x] = sq; __syncthreads();
    for (int off = 64; off > 0; off >>= 1) {
        if (threadIdx.x < off) { s1[threadIdx.x] += s1[threadIdx.x+off];
                                 s2[threadIdx.x] += s2[threadIdx.x+off]; }
        __syncthreads();
    }
    float mu  = s1[0] * (1.f/Dm);
    float var = s2[0] * (1.f/Dm) - mu*mu;
    float rstd = rsqrtf(var + EPSf);
#pragma unroll
    for (int i = 0; i < 4; i++) {
        int c = threadIdx.x + i*128;
        store3(yr + 3*c, (v[i] - mu) * rstd * g[c] + b[c]);
    }
}

__global__ void k_lossrow(const float* __restrict__ logits, const int* __restrict__ tgt,
                          float* __restrict__ lr) {
    __shared__ float red[256];
    int row = blockIdx.x;
    const float* l = logits + (size_t)row * Vn;
    float mx = -1e38f;
    for (int c = threadIdx.x; c < Vn; c += 256) mx = fmaxf(mx, l[c]);
    red[threadIdx.x] = mx; __syncthreads();
    for (int off = 128; off > 0; off >>= 1) {
        if (threadIdx.x < off) red[threadIdx.x] = fmaxf(red[threadIdx.x], red[threadIdx.x+off]);
        __syncthreads();
    }
    mx = red[0]; __syncthreads();
    float s = 0.f;
    for (int c = threadIdx.x; c < Vn; c += 256) s += __expf(l[c] - mx);
    red[threadIdx.x] = s; __syncthreads();
    for (int off = 128; off > 0; off >>= 1) {
        if (threadIdx.x < off) red[threadIdx.x] += red[threadIdx.x+off];
        __syncthreads();
    }
    if (threadIdx.x == 0)
        lr[row] = mx + logf(red[0]) - l[tgt[row]];
}

__global__ void k_lossreduce(const float* __restrict__ lr, float* __restrict__ out) {
    __shared__ float red[256];
    float s = 0.f;
    for (int i = threadIdx.x; i < NT; i += 256) s += lr[i];
    red[threadIdx.x] = s; __syncthreads();
    for (int off = 128; off > 0; off >>= 1) {
        if (threadIdx.x < off) red[threadIdx.x] += red[threadIdx.x+off];
        __syncthreads();
    }
    if (threadIdx.x == 0) *out = red[0] / (float)NT;
}

// ---------------- host -------------------------------------------------------

extern "C" void kernel_launch(void* const* d_in, const int* in_sizes, int n_in,
                              void* d_out, int out_size) {
    const int*   idx  = (const int*)  d_in[0];
    const int*   tgt  = (const int*)  d_in[1];
    const float* tok  = (const float*)d_in[2];
    const float* pos  = (const float*)d_in[3];
    const float* uqw  = (const float*)d_in[4];
    const float* uqb  = (const float*)d_in[5];
    const float* upw  = (const float*)d_in[6];
    const float* upb  = (const float*)d_in[7];
    const float* mqw  = (const float*)d_in[8];
    const float* mqb  = (const float*)d_in[9];
    const float* mpw  = (const float*)d_in[10];
    const float* mpb  = (const float*)d_in[11];
    const float* w1   = (const float*)d_in[12];
    const float* b1   = (const float*)d_in[13];
    const float* w2   = (const float*)d_in[14];
    const float* b2   = (const float*)d_in[15];
    const float* g1   = (const float*)d_in[16];
    const float* bb1  = (const float*)d_in[17];
    const float* g2   = (const float*)d_in[18];
    const float* bb2  = (const float*)d_in[19];
    const float* lnfg = (const float*)d_in[20];
    const float* lnfb = (const float*)d_in[21];
    const float* wout = (const float*)d_in[22];
    const float* bout = (const float*)d_in[23];

    float *x, *x2, *qkv, *lr, *lfb;
    __nv_bfloat16 *xn3, *at3, *ff3;
    __nv_bfloat16 *wuq, *wmq, *wup, *wmp, *ww1, *ww2, *wwo;
    cudaGetSymbolAddress((void**)&x,      g_x);
    cudaGetSymbolAddress((void**)&x2,     g_x2);
    cudaGetSymbolAddress((void**)&qkv,    g_qkv);
    cudaGetSymbolAddress((void**)&lr,     g_lossrow);
    cudaGetSymbolAddress((void**)&lfb,    g_lfb);
    cudaGetSymbolAddress((void**)&xn3,    g_xn3);
    cudaGetSymbolAddress((void**)&at3,    g_at3);
    cudaGetSymbolAddress((void**)&ff3,    g_ff3);
    cudaGetSymbolAddress((void**)&wuq,    g_w3_uqkv);
    cudaGetSymbolAddress((void**)&wmq,    g_w3_mqkv);
    cudaGetSymbolAddress((void**)&wup,    g_w3_uproj);
    cudaGetSymbolAddress((void**)&wmp,    g_w3_mproj);
    cudaGetSymbolAddress((void**)&ww1,    g_w3_w1);
    cudaGetSymbolAddress((void**)&ww2,    g_w3_w2);
    cudaGetSymbolAddress((void**)&wwo,    g_w3_wout);

    const int ATT_SM = (64*36 + 32*520 + 64*68) * 4;        // 93184
    cudaFuncSetAttribute(k_attn_fused, cudaFuncAttributeMaxDynamicSharedMemorySize, ATT_SM);
    const int SM_Q   = 2*(64*72*2  + 64*136*2);             // 53248  (MT2, 2-stage)
    const int SM_P   = 3*(64*72*2  + 64*136*2);             // 79872  (MT2, 3-stage)
    const int SM_F   = 3*(128*72*2 + 64*136*2);             // 107520 (MT4, 3-stage)
    cudaFuncSetAttribute((const void*)&k_mma<2,3,2>, cudaFuncAttributeMaxDynamicSharedMemorySize, SM_Q);
    cudaFuncSetAttribute((const void*)&k_mma<2,2,3>, cudaFuncAttributeMaxDynamicSharedMemorySize, SM_P);
    cudaFuncSetAttribute((const void*)&k_mma<4,2,3>, cudaFuncAttributeMaxDynamicSharedMemorySize, SM_F);

    // launch order: ncu (-s 5 -c 1) captures launch index 3 -------------------
    k_cvt_w<<<dim3(512, 1, Lnum*3), 256>>>(uqw, wuq, Dm, Dm,             // 0
        (long long)Dm*Dm, (long long)K3D*Dm);
    k_embed<<<NT, 128>>>(idx, tok, pos, x);                               // 1
    k_layernorm3<<<NT, 128>>>(x, g1, bb1, xn3);                           // 2
    k_mma<2,3,2><<<dim3(Dm/128, NT/64, 3), 128, SM_Q>>>(                  // 3 <- profiled
        xn3, wuq, uqb, nullptr, qkv, nullptr, Dm, K3D,
        (long long)K3D*Dm, (long long)Dm, (long long)NT*Dm, 0);
    // remaining conversions
    k_cvt_w<<<dim3(512, 1, Lnum), 256>>>(upw, wup, Dm, Dm,
        (long long)Dm*Dm, (long long)K3D*Dm);
    k_cvt_w<<<dim3(2048, 1, Lnum), 256>>>(w1, ww1, Dm, DFn,
        (long long)Dm*DFn, (long long)K3D*DFn);
    k_cvt_w<<<dim3(2048, 1, Lnum), 256>>>(w2, ww2, DFn, Dm,
        (long long)DFn*Dm, (long long)K3F*Dm);
    k_cvt_w<<<dim3(512, 1, Lnum*3), 256>>>(mqw, wmq, Dm, Dm,
        (long long)Dm*Dm, (long long)K3D*Dm);
    k_cvt_w<<<dim3(512, 1, Lnum), 256>>>(mpw, wmp, Dm, Dm,
        (long long)Dm*Dm, (long long)K3D*Dm);
    k_cvt_w<<<dim3(16384, 1, 1), 256>>>(wout, wwo, Dm, Vn, 0, 0);

    for (int l = 0; l < Lnum; l++) {
        for (int half = 0; half < 2; half++) {
            const __nv_bfloat16* qw3 = (half == 0 ? wuq : wmq) + (size_t)l * 3 * K3D * Dm;
            const __nv_bfloat16* pw3 = (half == 0 ? wup : wmp) + (size_t)l * K3D * Dm;
            const float* qb = (half == 0 ? uqb : mqb) + (size_t)l * 3 * Dm;
            const float* pb = (half == 0 ? upb : mpb) + (size_t)l * Dm;
            int causal = half;

            if (!(l == 0 && half == 0)) {
                k_layernorm3<<<NT, 128>>>(x, g1 + (size_t)l*Dm, bb1 + (size_t)l*Dm, xn3);
                k_mma<2,3,2><<<dim3(Dm/128, NT/64, 3), 128, SM_Q>>>(
                    xn3, qw3, qb, nullptr, qkv, nullptr, Dm, K3D,
                    (long long)K3D*Dm, (long long)Dm, (long long)NT*Dm, 0);
            }
            k_attn_fused<<<dim3(Tn/32, Bsz*Hn), 256, ATT_SM>>>(qkv, at3, causal);
            k_mma<2,2,3><<<dim3(Dm/128, NT/64, 1), 128, SM_P>>>(
                at3, pw3, pb, x, x2, nullptr, Dm, K3D, 0, 0, 0, 0);

            k_layernorm3<<<NT, 128>>>(x2, g2 + (size_t)l*Dm, bb2 + (size_t)l*Dm, xn3);
            k_mma<4,2,3><<<dim3(DFn/128, NT/128, 1), 128, SM_F>>>(
                xn3, ww1 + (size_t)l*K3D*DFn, b1 + (size_t)l*DFn, nullptr,
                nullptr, ff3, DFn, K3D, 0, 0, 0, 1);
            k_mma<2,2,3><<<dim3(Dm/128, NT/64, 1), 128, SM_P>>>(
                ff3, ww2 + (size_t)l*K3F*Dm, b2 + (size_t)l*Dm, x2, x, nullptr,
                Dm, K3F, 0, 0, 0, 0);
        }
    }

    k_layernorm3<<<NT, 128>>>(x, lnfg, lnfb, xn3);

    long long total = (long long)NT * Vn;
    float* logits = ((long long)out_size >= total) ? (float*)d_out : lfb;
    k_mma<4,2,3><<<dim3(Vn/128, NT/128, 1), 128, SM_F>>>(
        xn3, wwo, bout, nullptr, logits, nullptr, Vn, K3D, 0, 0, 0, 0);

    k_lossrow<<<NT, 256>>>(logits, tgt, lr);

    float* lossdst;
    if ((long long)out_size >= total + 1)      lossdst = (float*)d_out + total;
    else if ((long long)out_size < total)      lossdst = (float*)d_out;
    else                                       lossdst = lr;
    k_lossreduce<<<1, 256>>>(lr, lossdst);
}

// round 17
// speedup vs baseline: 1.1147x; 1.0321x over previous
#include <cuda_runtime.h>
#include <cuda_bf16.h>
#include <math.h>
#include <stdint.h>

#define Bsz 4
#define Tn  512
#define Dm  512
#define Hn  8
#define HSz 64
#define Lnum 8
#define Vn  32000
#define DFn 2048
#define NT  (Bsz*Tn)
#define EPSf 1e-5f
#define K3D (3*Dm)     // 1536
#define K3F (3*DFn)    // 6144

// ---------------- scratch ----------------------------------------------------
__device__ float g_x [NT*Dm];
__device__ float g_x2[NT*Dm];
__device__ float g_qkv[3*NT*Dm];
__device__ float g_lossrow[NT];
__device__ float g_lfb[(size_t)NT*Vn];

__device__ __nv_bfloat16 g_xn3 [NT*K3D];
__device__ __nv_bfloat16 g_at3 [NT*K3D];
__device__ __nv_bfloat16 g_ff3 [NT*K3F];

__device__ __nv_bfloat16 g_w3_uqkv [Lnum*3*(size_t)K3D*Dm];
__device__ __nv_bfloat16 g_w3_mqkv [Lnum*3*(size_t)K3D*Dm];
__device__ __nv_bfloat16 g_w3_uproj[Lnum*(size_t)K3D*Dm];
__device__ __nv_bfloat16 g_w3_mproj[Lnum*(size_t)K3D*Dm];
__device__ __nv_bfloat16 g_w3_w1   [Lnum*(size_t)K3D*DFn];
__device__ __nv_bfloat16 g_w3_w2   [Lnum*(size_t)K3F*Dm];
__device__ __nv_bfloat16 g_w3_wout [(size_t)K3D*Vn];

// ---------------- helpers ----------------------------------------------------

__device__ __forceinline__ float gelu_f(float v) {
    return 0.5f * v * (1.f + erff(v * 0.70710678118654752f));
}
__device__ __forceinline__ void store3(__nv_bfloat16* p, float v) {
    __nv_bfloat16 h = __float2bfloat16_rn(v);
    __nv_bfloat16 l = __float2bfloat16_rn(v - __bfloat162float(h));
    p[0] = h; p[1] = h; p[2] = l;
}
__device__ __forceinline__ uint32_t smem_u32(const void* p) {
    uint32_t a;
    asm("{ .reg .u64 t; cvta.to.shared.u64 t, %1; cvt.u32.u64 %0, t; }"
        : "=r"(a) : "l"(p));
    return a;
}
__device__ __forceinline__ void cp16(uint32_t dst, const void* src) {
    asm volatile("cp.async.cg.shared.global [%0], [%1], 16;"
                 :: "r"(dst), "l"(src) : "memory");
}
#define CP_COMMIT()  asm volatile("cp.async.commit_group;" ::: "memory")
template<int Nw> __device__ __forceinline__ void cp_wait() {
    asm volatile("cp.async.wait_group %0;" :: "n"(Nw) : "memory");
}
__device__ __forceinline__ void ldsm_x4(uint32_t& r0, uint32_t& r1, uint32_t& r2,
                                        uint32_t& r3, uint32_t a) {
    asm volatile("ldmatrix.sync.aligned.m8n8.x4.shared.b16 {%0,%1,%2,%3}, [%4];"
                 : "=r"(r0), "=r"(r1), "=r"(r2), "=r"(r3) : "r"(a));
}
__device__ __forceinline__ void ldsm_x4t(uint32_t& r0, uint32_t& r1, uint32_t& r2,
                                         uint32_t& r3, uint32_t a) {
    asm volatile("ldmatrix.sync.aligned.m8n8.x4.trans.shared.b16 {%0,%1,%2,%3}, [%4];"
                 : "=r"(r0), "=r"(r1), "=r"(r2), "=r"(r3) : "r"(a));
}
__device__ __forceinline__ void mma16816(float* c, const uint32_t* a, const uint32_t* b) {
    asm volatile("mma.sync.aligned.m16n8k16.row.col.f32.bf16.bf16.f32 "
                 "{%0,%1,%2,%3},{%4,%5,%6,%7},{%8,%9},{%0,%1,%2,%3};"
                 : "+f"(c[0]), "+f"(c[1]), "+f"(c[2]), "+f"(c[3])
                 : "r"(a[0]), "r"(a[1]), "r"(a[2]), "r"(a[3]), "r"(b[0]), "r"(b[1]));
}

// ---------------- weight conversion ------------------------------------------
__global__ void k_cvt_w(const float* __restrict__ W, __nv_bfloat16* __restrict__ out,
                        int K, int N, long long inz, long long outz) {
    const float* Wp = W + (size_t)blockIdx.z * inz;
    __nv_bfloat16* op = out + (size_t)blockIdx.z * outz;
    long long total = (long long)K * N;
    for (long long i = (long long)blockIdx.x * blockDim.x + threadIdx.x; i < total;
         i += (long long)gridDim.x * blockDim.x) {
        int k = (int)(i / N), n = (int)(i % N);
        float v = Wp[i];
        __nv_bfloat16 h = __float2bfloat16_rn(v);
        __nv_bfloat16 l = __float2bfloat16_rn(v - __bfloat162float(h));
        op[(size_t)(3*k+0)*N + n] = h;
        op[(size_t)(3*k+1)*N + n] = l;
        op[(size_t)(3*k+2)*N + n] = h;
    }
}

// ---------------- tensor-core GEMM -------------------------------------------
// C[M,N] = A3[M,K3] @ W3[K3,N]. BM=MT*32, BN template (64/128), BK=64.
// 128 threads, 4 warps 2x2; warp tile (MT*16) x (BN/2). STG-stage cp.async.
template<int MT, int MINB, int STG, int BN>
__global__ void __launch_bounds__(128, MINB) k_mma(
    const __nv_bfloat16* __restrict__ A3, const __nv_bfloat16* __restrict__ W3,
    const float* __restrict__ bias, const float* __restrict__ res,
    float* __restrict__ outF, __nv_bfloat16* __restrict__ out3,
    int N, int K3, long long wz, long long bz, long long cz, int gelu) {
    constexpr int BM   = MT * 32;
    constexpr int AROW = 72;                 // padded row elems (64 + 8)
    constexpr int BROW = BN + 8;
    constexpr int AST  = BM * AROW * 2;
    constexpr int BST  = 64 * BROW * 2;
    constexpr int SS   = AST + BST;
    constexpr int NTIL = BN / 16;            // nt tiles per warp (8-col each)
    constexpr int H2N  = BN / 32;            // ldsm_x4t groups per warp
    constexpr int BNW  = BN / 8;             // b elems-of-8 per row
    extern __shared__ char dynsm[];
    uint32_t sbase = smem_u32(dynsm);

    if (wz) {
        W3   += (size_t)blockIdx.z * wz;
        bias += (size_t)blockIdx.z * bz;
        outF += (size_t)blockIdx.z * cz;
    }
    int tid = threadIdx.x, lane = tid & 31, warp = tid >> 5;
    int wm = warp >> 1, wn = warp & 1;
    int bm = blockIdx.y * BM, bn = blockIdx.x * BN;

    float acc[MT][NTIL][4];
#pragma unroll
    for (int i = 0; i < MT; i++)
#pragma unroll
        for (int j = 0; j < NTIL; j++)
#pragma unroll
            for (int k = 0; k < 4; k++) acc[i][j][k] = 0.f;

    const int KT = K3 / 64;

    auto Aaddr = [&](int s, int r, int c) { return sbase + s*SS + (r*AROW + c)*2; };
    auto Baddr = [&](int s, int k, int n) { return sbase + s*SS + AST + (k*BROW + n)*2; };

    auto fill = [&](int s, int t) {
        int k0 = t * 64;
#pragma unroll
        for (int i = 0; i < BM/16; i++) {           // A: BM x 64 elems
            int id = tid + i * 128;
            int ar = id >> 3, ac = (id & 7) * 8;
            cp16(Aaddr(s, ar, ac), A3 + (size_t)(bm + ar) * K3 + k0 + ac);
        }
#pragma unroll
        for (int i = 0; i < BN/16; i++) {           // B: 64 x BN elems
            int id = tid + i * 128;
            int kk = id / BNW, nn = (id % BNW) * 8;
            cp16(Baddr(s, kk, nn), W3 + (size_t)(k0 + kk) * N + bn + nn);
        }
    };

    fill(0, 0); CP_COMMIT();
    if (STG == 3) { fill(1, 1); CP_COMMIT(); }

    for (int t = 0; t < KT; t++) {
        int s = t % STG;
        if (STG == 2) {
            cp_wait<0>();
            __syncthreads();
            if (t + 1 < KT) { fill((t + 1) % STG, t + 1); CP_COMMIT(); }
        } else {
            if (t + 1 < KT) cp_wait<1>(); else cp_wait<0>();
            __syncthreads();
            if (t + 2 < KT) { fill((t + 2) % STG, t + 2); CP_COMMIT(); }
        }
#pragma unroll
        for (int kt = 0; kt < 4; kt++) {
            int k16 = kt * 16;
            uint32_t a[MT][4];
#pragma unroll
            for (int mt = 0; mt < MT; mt++)
                ldsm_x4(a[mt][0], a[mt][1], a[mt][2], a[mt][3],
                        Aaddr(s, wm*MT*16 + mt*16 + (lane & 15), k16 + ((lane >> 4) << 3)));
            uint32_t b[NTIL][2];
#pragma unroll
            for (int h2 = 0; h2 < H2N; h2++) {
                uint32_t r0, r1, r2, r3;
                ldsm_x4t(r0, r1, r2, r3,
                         Baddr(s, k16 + (lane & 15), wn*(BN/2) + h2*16 + ((lane >> 4) << 3)));
                b[h2*2][0] = r0; b[h2*2][1] = r1;
                b[h2*2+1][0] = r2; b[h2*2+1][1] = r3;
            }
#pragma unroll
            for (int mt = 0; mt < MT; mt++)
#pragma unroll
                for (int nt = 0; nt < NTIL; nt++)
                    mma16816(acc[mt][nt], a[mt], b[nt]);
        }
    }

    // epilogue
    int r = lane >> 2, cg = lane & 3;
#pragma unroll
    for (int mt = 0; mt < MT; mt++) {
        int row0 = bm + wm*MT*16 + mt*16 + r;
        int row1 = row0 + 8;
#pragma unroll
        for (int nt = 0; nt < NTIL; nt++) {
            int col = bn + wn*(BN/2) + nt*8 + cg*2;
            float v00 = acc[mt][nt][0] + bias[col];
            float v01 = acc[mt][nt][1] + bias[col+1];
            float v10 = acc[mt][nt][2] + bias[col];
            float v11 = acc[mt][nt][3] + bias[col+1];
            if (gelu) { v00 = gelu_f(v00); v01 = gelu_f(v01);
                        v10 = gelu_f(v10); v11 = gelu_f(v11); }
            if (res) {
                float2 q0 = *(const float2*)&res[(size_t)row0*N + col];
                float2 q1 = *(const float2*)&res[(size_t)row1*N + col];
                v00 += q0.x; v01 += q0.y; v10 += q1.x; v11 += q1.y;
            }
            if (outF) {
                *(float2*)&outF[(size_t)row0*N + col] = make_float2(v00, v01);
                *(float2*)&outF[(size_t)row1*N + col] = make_float2(v10, v11);
            }
            if (out3) {
                store3(out3 + (size_t)row0*3*N + 3*col,     v00);
                store3(out3 + (size_t)row0*3*N + 3*(col+1), v01);
                store3(out3 + (size_t)row1*3*N + 3*col,     v10);
                store3(out3 + (size_t)row1*3*N + 3*(col+1), v11);
            }
        }
    }
}

// ---------------- fused attention (unchanged) --------------------------------
__global__ void __launch_bounds__(256) k_attn_fused(
    const float* __restrict__ qkv, __nv_bfloat16* __restrict__ O3, int causal) {
    extern __shared__ float sm[];
    float* Qs = sm;                 // [64][36]
    float* Ss = Qs + 64*36;         // [32][520]
    float* KV = Ss + 32*520;        // [64][68]
    int bh = blockIdx.y, b = bh >> 3, h = bh & 7;
    int t0 = blockIdx.x * 32;
    int tid = threadIdx.x;
    const float* Qg = qkv + (size_t)(b*Tn + t0)*Dm + h*HSz;
    const float* Kg = qkv + (size_t)NT*Dm + (size_t)b*Tn*Dm + h*HSz;
    const float* Vg = qkv + (size_t)2*NT*Dm + (size_t)b*Tn*Dm + h*HSz;

#pragma unroll
    for (int i = 0; i < 8; i++) {
        int id = tid + i*256;
        int k = id & 63, r2 = id >> 6;
        Qs[k*36 + r2] = Qg[(size_t)r2 * Dm + k];
    }
    int Lmax = causal ? (t0 + 32) : Tn;
    int nch = (Lmax + 63) >> 6;
    int Lpad = nch << 6;
    int tx = tid & 15, ty = tid >> 4;

    for (int c = 0; c < nch; c++) {
        int s0 = c << 6;
        __syncthreads();
#pragma unroll
        for (int i = 0; i < 16; i++) {
            int id = tid + i*256;
            int k = id & 63, s = id >> 6;
            KV[k*68 + s] = Kg[(size_t)(s0 + s) * Dm + k];
        }
        __syncthreads();
        float a0[4] = {0,0,0,0}, a1[4] = {0,0,0,0};
#pragma unroll 8
        for (int k = 0; k < 64; k++) {
            float q0 = Qs[k*36 + ty*2], q1 = Qs[k*36 + ty*2 + 1];
            float4 kv = *(const float4*)&KV[k*68 + tx*4];
            a0[0] = fmaf(q0, kv.x, a0[0]); a0[1] = fmaf(q0, kv.y, a0[1]);
            a0[2] = fmaf(q0, kv.z, a0[2]); a0[3] = fmaf(q0, kv.w, a0[3]);
            a1[0] = fmaf(q1, kv.x, a1[0]); a1[1] = fmaf(q1, kv.y, a1[1]);
            a1[2] = fmaf(q1, kv.z, a1[2]); a1[3] = fmaf(q1, kv.w, a1[3]);
        }
        int t_a = t0 + ty*2, t_b = t_a + 1;
#pragma unroll
        for (int j = 0; j < 4; j++) {
            int s = s0 + tx*4 + j;
            float v0 = a0[j] * 0.125f, v1 = a1[j] * 0.125f;
            if (causal && s > t_a) v0 = -1e30f;
            if (causal && s > t_b) v1 = -1e30f;
            Ss[(ty*2)*520 + s]   = v0;
            Ss[(ty*2+1)*520 + s] = v1;
        }
    }
    __syncthreads();

    int warp = tid >> 5, lane = tid & 31;
    for (int r2 = warp; r2 < 32; r2 += 8) {
        float mx = -1e38f;
        for (int jc = lane; jc < Lpad; jc += 32) mx = fmaxf(mx, Ss[r2*520 + jc]);
#pragma unroll
        for (int o = 16; o; o >>= 1) mx = fmaxf(mx, __shfl_xor_sync(~0u, mx, o));
        float sum = 0.f;
        for (int jc = lane; jc < Lpad; jc += 32) {
            float e = __expf(Ss[r2*520 + jc] - mx);
            Ss[r2*520 + jc] = e; sum += e;
        }
#pragma unroll
        for (int o = 16; o; o >>= 1) sum += __shfl_xor_sync(~0u, sum, o);
        float inv = 1.f / sum;
        for (int jc = lane; jc < Lpad; jc += 32) Ss[r2*520 + jc] *= inv;
    }

    float o0[4] = {0,0,0,0}, o1[4] = {0,0,0,0};
    for (int c = 0; c < nch; c++) {
        int s0 = c << 6;
        __syncthreads();
#pragma unroll
        for (int i = 0; i < 16; i++) {
            int id = tid + i*256;
            int d = id & 63, s = id >> 6;
            KV[s*68 + d] = Vg[(size_t)(s0 + s) * Dm + d];
        }
        __syncthreads();
#pragma unroll 8
        for (int s = 0; s < 64; s++) {
            float p0 = Ss[(ty*2)*520 + s0 + s];
            float p1 = Ss[(ty*2+1)*520 + s0 + s];
            float4 vv = *(const float4*)&KV[s*68 + tx*4];
            o0[0] = fmaf(p0, vv.x, o0[0]); o0[1] = fmaf(p0, vv.y, o0[1]);
            o0[2] = fmaf(p0, vv.z, o0[2]); o0[3] = fmaf(p0, vv.w, o0[3]);
            o1[0] = fmaf(p1, vv.x, o1[0]); o1[1] = fmaf(p1, vv.y, o1[1]);
            o1[2] = fmaf(p1, vv.z, o1[2]); o1[3] = fmaf(p1, vv.w, o1[3]);
        }
    }
    int row0 = b*Tn + t0 + ty*2, row1 = row0 + 1;
#pragma unroll
    for (int j = 0; j < 4; j++) {
        int col = h*HSz + tx*4 + j;
        store3(O3 + (size_t)row0*K3D + 3*col, o0[j]);
        store3(O3 + (size_t)row1*K3D + 3*col, o1[j]);
    }
}

// ---------------- other kernels ----------------------------------------------

__global__ void k_embed(const int* __restrict__ idx, const float* __restrict__ tok,
                        const float* __restrict__ pos, float* __restrict__ x) {
    int row = blockIdx.x;
    int t = row % Tn;
    int tk = idx[row];
    const float* te = tok + (size_t)tk * Dm;
    const float* pe = pos + (size_t)t  * Dm;
    float* xr = x + (size_t)row * Dm;
    for (int c = threadIdx.x; c < Dm; c += blockDim.x)
        xr[c] = te[c] + pe[c];
}

__global__ void k_layernorm3(const float* __restrict__ x, const float* __restrict__ g,
                             const float* __restrict__ b, __nv_bfloat16* __restrict__ y3) {
    __shared__ float s1[128], s2[128];
    int row = blockIdx.x;
    const float* xr = x + (size_t)row * Dm;
    __nv_bfloat16* yr = y3 + (size_t)row * K3D;
    float v[4], sum = 0.f, sq = 0.f;
#pragma unroll
    for (int i = 0; i < 4; i++) {
        v[i] = xr[threadIdx.x + i*128];
        sum += v[i]; sq += v[i]*v[i];
    }
    s1[threadIdx.x] = sum; s2[threadIdx.x] = sq; __syncthreads();
    for (int off = 64; off > 0; off >>= 1) {
        if (threadIdx.x < off) { s1[threadIdx.x] += s1[threadIdx.x+off];
                                 s2[threadIdx.x] += s2[threadIdx.x+off]; }
        __syncthreads();
    }
    float mu  = s1[0] * (1.f/Dm);
    float var = s2[0] * (1.f/Dm) - mu*mu;
    float rstd = rsqrtf(var + EPSf);
#pragma unroll
    for (int i = 0; i < 4; i++) {
        int c = threadIdx.x + i*128;
        store3(yr + 3*c, (v[i] - mu) * rstd * g[c] + b[c]);
    }
}

__global__ void k_lossrow(const float* __restrict__ logits, const int* __restrict__ tgt,
                          float* __restrict__ lr) {
    __shared__ float red[256];
    int row = blockIdx.x;
    const float* l = logits + (size_t)row * Vn;
    float mx = -1e38f;
    for (int c = threadIdx.x; c < Vn; c += 256) mx = fmaxf(mx, l[c]);
    red[threadIdx.x] = mx; __syncthreads();
    for (int off = 128; off > 0; off >>= 1) {
        if (threadIdx.x < off) red[threadIdx.x] = fmaxf(red[threadIdx.x], red[threadIdx.x+off]);
        __syncthreads();
    }
    mx = red[0]; __syncthreads();
    float s = 0.f;
    for (int c = threadIdx.x; c < Vn; c += 256) s += __expf(l[c] - mx);
    red[threadIdx.x] = s; __syncthreads();
    for (int off = 128; off > 0; off >>= 1) {
        if (threadIdx.x < off) red[threadIdx.x] += red[threadIdx.x+off];
        __syncthreads();
    }
    if (threadIdx.x == 0)
        lr[row] = mx + logf(red[0]) - l[tgt[row]];
}

__global__ void k_lossreduce(const float* __restrict__ lr, float* __restrict__ out) {
    __shared__ float red[256];
    float s = 0.f;
    for (int i = threadIdx.x; i < NT; i += 256) s += lr[i];
    red[threadIdx.x] = s; __syncthreads();
    for (int off = 128; off > 0; off >>= 1) {
        if (threadIdx.x < off) red[threadIdx.x] += red[threadIdx.x+off];
        __syncthreads();
    }
    if (threadIdx.x == 0) *out = red[0] / (float)NT;
}

// ---------------- host -------------------------------------------------------

extern "C" void kernel_launch(void* const* d_in, const int* in_sizes, int n_in,
                              void* d_out, int out_size) {
    const int*   idx  = (const int*)  d_in[0];
    const int*   tgt  = (const int*)  d_in[1];
    const float* tok  = (const float*)d_in[2];
    const float* pos  = (const float*)d_in[3];
    const float* uqw  = (const float*)d_in[4];
    const float* uqb  = (const float*)d_in[5];
    const float* upw  = (const float*)d_in[6];
    const float* upb  = (const float*)d_in[7];
    const float* mqw  = (const float*)d_in[8];
    const float* mqb  = (const float*)d_in[9];
    const float* mpw  = (const float*)d_in[10];
    const float* mpb  = (const float*)d_in[11];
    const float* w1   = (const float*)d_in[12];
    const float* b1   = (const float*)d_in[13];
    const float* w2   = (const float*)d_in[14];
    const float* b2   = (const float*)d_in[15];
    const float* g1   = (const float*)d_in[16];
    const float* bb1  = (const float*)d_in[17];
    const float* g2   = (const float*)d_in[18];
    const float* bb2  = (const float*)d_in[19];
    const float* lnfg = (const float*)d_in[20];
    const float* lnfb = (const float*)d_in[21];
    const float* wout = (const float*)d_in[22];
    const float* bout = (const float*)d_in[23];

    float *x, *x2, *qkv, *lr, *lfb;
    __nv_bfloat16 *xn3, *at3, *ff3;
    __nv_bfloat16 *wuq, *wmq, *wup, *wmp, *ww1, *ww2, *wwo;
    cudaGetSymbolAddress((void**)&x,      g_x);
    cudaGetSymbolAddress((void**)&x2,     g_x2);
    cudaGetSymbolAddress((void**)&qkv,    g_qkv);
    cudaGetSymbolAddress((void**)&lr,     g_lossrow);
    cudaGetSymbolAddress((void**)&lfb,    g_lfb);
    cudaGetSymbolAddress((void**)&xn3,    g_xn3);
    cudaGetSymbolAddress((void**)&at3,    g_at3);
    cudaGetSymbolAddress((void**)&ff3,    g_ff3);
    cudaGetSymbolAddress((void**)&wuq,    g_w3_uqkv);
    cudaGetSymbolAddress((void**)&wmq,    g_w3_mqkv);
    cudaGetSymbolAddress((void**)&wup,    g_w3_uproj);
    cudaGetSymbolAddress((void**)&wmp,    g_w3_mproj);
    cudaGetSymbolAddress((void**)&ww1,    g_w3_w1);
    cudaGetSymbolAddress((void**)&ww2,    g_w3_w2);
    cudaGetSymbolAddress((void**)&wwo,    g_w3_wout);

    const int ATT_SM = (64*36 + 32*520 + 64*68) * 4;        // 93184
    cudaFuncSetAttribute(k_attn_fused, cudaFuncAttributeMaxDynamicSharedMemorySize, ATT_SM);
    const int SM_Q   = 2*(64*72*2  + 64*136*2);             // 53248 (MT2, 2stg, BN128)
    const int SM_P   = 3*(64*72*2  + 64*72*2);              // 55296 (MT2, 3stg, BN64)
    const int SM_F   = 3*(128*72*2 + 64*136*2);             // 107520 (MT4, 3stg, BN128)
    cudaFuncSetAttribute((const void*)&k_mma<2,3,2,128>, cudaFuncAttributeMaxDynamicSharedMemorySize, SM_Q);
    cudaFuncSetAttribute((const void*)&k_mma<2,4,3,64>,  cudaFuncAttributeMaxDynamicSharedMemorySize, SM_P);
    cudaFuncSetAttribute((const void*)&k_mma<4,2,3,128>, cudaFuncAttributeMaxDynamicSharedMemorySize, SM_F);

    // launch order: ncu (-s 5 -c 1) captures launch index 3 -------------------
    k_cvt_w<<<dim3(512, 1, Lnum*3), 256>>>(uqw, wuq, Dm, Dm,             // 0
        (long long)Dm*Dm, (long long)K3D*Dm);
    k_embed<<<NT, 128>>>(idx, tok, pos, x);                               // 1
    k_layernorm3<<<NT, 128>>>(x, g1, bb1, xn3);                           // 2
    k_mma<2,3,2,128><<<dim3(Dm/128, NT/64, 3), 128, SM_Q>>>(              // 3 <- profiled
        xn3, wuq, uqb, nullptr, qkv, nullptr, Dm, K3D,
        (long long)K3D*Dm, (long long)Dm, (long long)NT*Dm, 0);
    // remaining conversions
    k_cvt_w<<<dim3(512, 1, Lnum), 256>>>(upw, wup, Dm, Dm,
        (long long)Dm*Dm, (long long)K3D*Dm);
    k_cvt_w<<<dim3(2048, 1, Lnum), 256>>>(w1, ww1, Dm, DFn,
        (long long)Dm*DFn, (long long)K3D*DFn);
    k_cvt_w<<<dim3(2048, 1, Lnum), 256>>>(w2, ww2, DFn, Dm,
        (long long)DFn*Dm, (long long)K3F*Dm);
    k_cvt_w<<<dim3(512, 1, Lnum*3), 256>>>(mqw, wmq, Dm, Dm,
        (long long)Dm*Dm, (long long)K3D*Dm);
    k_cvt_w<<<dim3(512, 1, Lnum), 256>>>(mpw, wmp, Dm, Dm,
        (long long)Dm*Dm, (long long)K3D*Dm);
    k_cvt_w<<<dim3(16384, 1, 1), 256>>>(wout, wwo, Dm, Vn, 0, 0);

    for (int l = 0; l < Lnum; l++) {
        for (int half = 0; half < 2; half++) {
            const __nv_bfloat16* qw3 = (half == 0 ? wuq : wmq) + (size_t)l * 3 * K3D * Dm;
            const __nv_bfloat16* pw3 = (half == 0 ? wup : wmp) + (size_t)l * K3D * Dm;
            const float* qb = (half == 0 ? uqb : mqb) + (size_t)l * 3 * Dm;
            const float* pb = (half == 0 ? upb : mpb) + (size_t)l * Dm;
            int causal = half;

            if (!(l == 0 && half == 0)) {
                k_layernorm3<<<NT, 128>>>(x, g1 + (size_t)l*Dm, bb1 + (size_t)l*Dm, xn3);
                k_mma<2,3,2,128><<<dim3(Dm/128, NT/64, 3), 128, SM_Q>>>(
                    xn3, qw3, qb, nullptr, qkv, nullptr, Dm, K3D,
                    (long long)K3D*Dm, (long long)Dm, (long long)NT*Dm, 0);
            }
            k_attn_fused<<<dim3(Tn/32, Bsz*Hn), 256, ATT_SM>>>(qkv, at3, causal);
            k_mma<2,4,3,64><<<dim3(Dm/64, NT/64, 1), 128, SM_P>>>(
                at3, pw3, pb, x, x2, nullptr, Dm, K3D, 0, 0, 0, 0);

            k_layernorm3<<<NT, 128>>>(x2, g2 + (size_t)l*Dm, bb2 + (size_t)l*Dm, xn3);
            k_mma<4,2,3,128><<<dim3(DFn/128, NT/128, 1), 128, SM_F>>>(
                xn3, ww1 + (size_t)l*K3D*DFn, b1 + (size_t)l*DFn, nullptr,
                nullptr, ff3, DFn, K3D, 0, 0, 0, 1);
            k_mma<2,4,3,64><<<dim3(Dm/64, NT/64, 1), 128, SM_P>>>(
                ff3, ww2 + (size_t)l*K3F*Dm, b2 + (size_t)l*Dm, x2, x, nullptr,
                Dm, K3F, 0, 0, 0, 0);
        }
    }

    k_layernorm3<<<NT, 128>>>(x, lnfg, lnfb, xn3);

    long long total = (long long)NT * Vn;
    float* logits = ((long long)out_size >= total) ? (float*)d_out : lfb;
    k_mma<4,2,3,128><<<dim3(Vn/128, NT/128, 1), 128, SM_F>>>(
        xn3, wwo, bout, nullptr, logits, nullptr, Vn, K3D, 0, 0, 0, 0);

    k_lossrow<<<NT, 256>>>(logits, tgt, lr);

    float* lossdst;
    if ((long long)out_size >= total + 1)      lossdst = (float*)d_out + total;
    else if ((long long)out_size < total)      lossdst = (float*)d_out;
    else                                       lossdst = lr;
    k_lossreduce<<<1, 256>>>(lr, lossdst);
}